// round 12
// baseline (speedup 1.0000x reference)
#include <cuda_runtime.h>
#include <cuda_bf16.h>
#include <math.h>
#include <stdint.h>

// Problem dimensions (fixed by the dataset)
#define SS 512   // timesteps
#define BB 128   // batch
#define DD 256   // input dim
#define HH 512   // hidden
#define GG 2048  // 4*H (gate-interleaved: col n = j*4 + gate)
#define BH (BB*HH)

// Device scratch (no runtime allocation allowed)
__device__ float g_bias[GG];                 // interleaved bias [2048]
__device__ __nv_bfloat16 g_UThi[GG*HH];      // U'^T hi  [2048 n][512 k] bf16
__device__ __nv_bfloat16 g_UTlo[GG*HH];      // U'^T lo
__device__ __nv_bfloat16 g_WThi[GG*DD];      // W'^T hi  [2048 n][256 k] bf16
__device__ __nv_bfloat16 g_WTlo[GG*DD];      // W'^T lo
__device__ __nv_bfloat16 g_xhi[(size_t)SS*BB*DD];  // x hi  [65536 m][256 k] bf16
__device__ __nv_bfloat16 g_xlo[(size_t)SS*BB*DD];  // x lo
__device__ __nv_bfloat16 g_hBhi[2*BB*HH];    // double-buffered h hi [2][128 b][512 k]
__device__ __nv_bfloat16 g_hBlo[2*BB*HH];    // double-buffered h lo
__device__ float g_mdhp[BH];                 // tanh(alpha@A - (beta*ts)@B + theta@C)
__device__ float g_c[BH];                    // final cell state (for finalize)
__device__ float g_xw[(size_t)SS*BB*GG];     // precomputed x@W' + b  (512 MB)
__device__ unsigned g_ctr4[4];               // per-rowgroup barrier counters

// ---------------------------------------------------------------------------
// helpers
// ---------------------------------------------------------------------------
__device__ __forceinline__ void mma_bf16(float* c, uint32_t a0, uint32_t a1,
                                         uint32_t a2, uint32_t a3,
                                         uint32_t b0, uint32_t b1) {
    asm volatile("mma.sync.aligned.m16n8k16.row.col.f32.bf16.bf16.f32 "
        "{%0,%1,%2,%3}, {%4,%5,%6,%7}, {%8,%9}, {%0,%1,%2,%3};"
        : "+f"(c[0]), "+f"(c[1]), "+f"(c[2]), "+f"(c[3])
        : "r"(a0), "r"(a1), "r"(a2), "r"(a3), "r"(b0), "r"(b1));
}
__device__ __forceinline__ void ldsm_x4(uint32_t* r, uint32_t addr) {
    asm volatile("ldmatrix.sync.aligned.m8n8.x4.shared.b16 {%0,%1,%2,%3}, [%4];"
        : "=r"(r[0]), "=r"(r[1]), "=r"(r[2]), "=r"(r[3]) : "r"(addr));
}
__device__ __forceinline__ void ldsm_x2(uint32_t& r0, uint32_t& r1, uint32_t addr) {
    asm volatile("ldmatrix.sync.aligned.m8n8.x2.shared.b16 {%0,%1}, [%2];"
        : "=r"(r0), "=r"(r1) : "r"(addr));
}
__device__ __forceinline__ uint32_t smem_cast(const void* p) {
    return (uint32_t)__cvta_generic_to_shared(p);
}

// ---------------------------------------------------------------------------
// Build bf16-split U'^T, W'^T (both [n][k], n gate-interleaved), and bias.
// ---------------------------------------------------------------------------
__global__ void prep_weights(const float* __restrict__ Wi, const float* __restrict__ Ui, const float* __restrict__ bi,
                             const float* __restrict__ Wf, const float* __restrict__ Uf, const float* __restrict__ bf,
                             const float* __restrict__ Wc, const float* __restrict__ Uc, const float* __restrict__ bc,
                             const float* __restrict__ Wo, const float* __restrict__ Uo, const float* __restrict__ bo)
{
    int idx = blockIdx.x * blockDim.x + threadIdx.x;
    int stride = gridDim.x * blockDim.x;
    for (int i = idx; i < HH * GG; i += stride) {
        {   // U'^T bf16 hi/lo: i = n*512 + k
            int n = i >> 9, k = i & 511;
            int j = n >> 2, g = n & 3;
            const float* U = (g == 0) ? Ui : (g == 1) ? Uf : (g == 2) ? Uc : Uo;
            float u = U[k * HH + j];
            __nv_bfloat16 hi = __float2bfloat16(u);
            g_UThi[i] = hi;
            g_UTlo[i] = __float2bfloat16(u - __bfloat162float(hi));
        }
        if (i < GG * DD) {   // W'^T bf16 hi/lo: i = n*256 + k
            int n = i >> 8, k = i & 255;
            int j = n >> 2, g = n & 3;
            const float* W = (g == 0) ? Wi : (g == 1) ? Wf : (g == 2) ? Wc : Wo;
            float w = W[k * HH + j];
            __nv_bfloat16 hi = __float2bfloat16(w);
            g_WThi[i] = hi;
            g_WTlo[i] = __float2bfloat16(w - __bfloat162float(hi));
        }
        if (i < GG) {
            int j = i >> 2, g = i & 3;
            const float* bptr = (g == 0) ? bi : (g == 1) ? bf : (g == 2) ? bc : bo;
            g_bias[i] = bptr[j];
        }
    }
}

// split x into bf16 hi/lo (16.7M elements, 4 per thread)
__global__ void xsplit(const float* __restrict__ x)
{
    size_t i = (size_t)blockIdx.x * blockDim.x + threadIdx.x;   // float4 index
    float4 v = *((const float4*)x + i);
    __nv_bfloat16 h0 = __float2bfloat16(v.x);
    __nv_bfloat16 h1 = __float2bfloat16(v.y);
    __nv_bfloat16 h2 = __float2bfloat16(v.z);
    __nv_bfloat16 h3 = __float2bfloat16(v.w);
    __nv_bfloat16 l0 = __float2bfloat16(v.x - __bfloat162float(h0));
    __nv_bfloat16 l1 = __float2bfloat16(v.y - __bfloat162float(h1));
    __nv_bfloat16 l2 = __float2bfloat16(v.z - __bfloat162float(h2));
    __nv_bfloat16 l3 = __float2bfloat16(v.w - __bfloat162float(h3));
    ushort4 ph = make_ushort4(__bfloat16_as_ushort(h0), __bfloat16_as_ushort(h1),
                              __bfloat16_as_ushort(h2), __bfloat16_as_ushort(h3));
    ushort4 pl = make_ushort4(__bfloat16_as_ushort(l0), __bfloat16_as_ushort(l1),
                              __bfloat16_as_ushort(l2), __bfloat16_as_ushort(l3));
    *((ushort4*)g_xhi + i) = ph;
    *((ushort4*)g_xlo + i) = pl;
}

// ---------------------------------------------------------------------------
// mdhp = tanh(alpha @ A - (beta*tspan) @ B + theta @ C)   [B,H]
// ---------------------------------------------------------------------------
__global__ void mdhp_kernel(const float* __restrict__ alpha, const float* __restrict__ beta,
                            const float* __restrict__ theta, const float* __restrict__ tspan,
                            const float* __restrict__ A, const float* __restrict__ Bm,
                            const float* __restrict__ C)
{
    int b = blockIdx.x;
    int j = threadIdx.x;   // 0..511
    __shared__ float sa[256], sb[256], st[16];
    float ts = tspan[b];
    if (j < 256) {
        sa[j] = alpha[b * 256 + j];
        sb[j] = beta[b * 256 + j] * ts;
    }
    if (j < 16) st[j] = theta[b * 16 + j];
    __syncthreads();
    float acc = 0.f;
    #pragma unroll 4
    for (int k = 0; k < 256; k++)
        acc += sa[k] * A[k * 512 + j] - sb[k] * Bm[k * 512 + j];
    #pragma unroll
    for (int k = 0; k < 16; k++)
        acc += st[k] * C[k * 512 + j];
    g_mdhp[b * 512 + j] = tanhf(acc);
}

// zero barrier counters + bf16-split h0 into g_hB buffer 0
__global__ void prep_state(const float* __restrict__ h0)
{
    int i = blockIdx.x * blockDim.x + threadIdx.x;
    if (i < 4) g_ctr4[i] = 0u;
    if (i < BB * HH) {
        float v = h0[i];                       // i = b*512 + k
        __nv_bfloat16 hi = __float2bfloat16(v);
        g_hBhi[i] = hi;
        g_hBlo[i] = __float2bfloat16(v - __bfloat162float(hi));
    }
}

// ---------------------------------------------------------------------------
// xW GEMM on mma.sync bf16 (2-way split, 3-term product) with ldmatrix:
//   g_xw[65536, 2048] = x[65536, 256] @ W'[256, 2048] + bias
// Block: 128x128 C tile, 256 threads = 8 warps (4 M x 2 N), warp tile 32x64.
// (unchanged from round 11 — measured 623us, tensor=54.5%)
// ---------------------------------------------------------------------------
#define ROWX 36   // uint32 words per padded row (32 data words = 64 bf16)
__global__ __launch_bounds__(256, 2) void xw_mma()
{
    extern __shared__ __align__(16) uint32_t xs[];
    uint32_t* a_hi = xs;                    // [128][36]
    uint32_t* a_lo = xs + 128 * ROWX;
    uint32_t* b_hi = xs + 2 * 128 * ROWX;
    uint32_t* b_lo = xs + 3 * 128 * ROWX;

    const int tid  = threadIdx.x;
    const int lane = tid & 31;
    const int wid  = tid >> 5;
    const int mbase = (wid & 3) * 32;       // 0,32,64,96
    const int nbase = (wid >> 2) * 64;      // 0,64
    const int r  = lane >> 2;               // 0..7
    const int tq = lane & 3;                // 0..3
    const int n0 = blockIdx.x * 128;
    const int m0 = blockIdx.y * 128;

    const uint32_t aRowOff = ((mbase + (lane & 15)) * ROWX + (lane >> 4) * 4) << 2;
    const uint32_t aHiB = smem_cast(a_hi) + aRowOff;
    const uint32_t aLoB = smem_cast(a_lo) + aRowOff;
    const uint32_t bRowOff = ((nbase + (lane & 7)) * ROWX + ((lane >> 3) & 1) * 4) << 2;
    const uint32_t bHiB = smem_cast(b_hi) + bRowOff;
    const uint32_t bLoB = smem_cast(b_lo) + bRowOff;
    const uint32_t FSTRIDE = (16 * ROWX) << 2;   // f: +16 rows
    const uint32_t JSTRIDE = (8 * ROWX) << 2;    // j: +8 rows

    float c[2][8][4];
    #pragma unroll
    for (int f = 0; f < 2; f++)
        #pragma unroll
        for (int j = 0; j < 8; j++)
            #pragma unroll
            for (int q = 0; q < 4; q++) c[f][j][q] = 0.f;

    for (int kc = 0; kc < 4; kc++) {
        const int k0 = kc * 64;
        #pragma unroll
        for (int q = 0; q < 4; q++) {
            int u = tid + q * 256;          // 0..1023
            int row = u >> 3;               // 0..127
            int c4  = u & 7;                // uint4 within row
            uint4 vah = *((const uint4*)(g_xhi + (size_t)(m0 + row) * DD + k0) + c4);
            uint4 val = *((const uint4*)(g_xlo + (size_t)(m0 + row) * DD + k0) + c4);
            uint4 vbh = *((const uint4*)(g_WThi + (size_t)(n0 + row) * DD + k0) + c4);
            uint4 vbl = *((const uint4*)(g_WTlo + (size_t)(n0 + row) * DD + k0) + c4);
            *(uint4*)(a_hi + row * ROWX + c4 * 4) = vah;
            *(uint4*)(a_lo + row * ROWX + c4 * 4) = val;
            *(uint4*)(b_hi + row * ROWX + c4 * 4) = vbh;
            *(uint4*)(b_lo + row * ROWX + c4 * 4) = vbl;
        }
        __syncthreads();

        #pragma unroll
        for (int ks = 0; ks < 4; ks++) {
            const uint32_t ksOff = ks * 32;          // 8 words
            uint32_t ah[2][4], al[2][4];
            ldsm_x4(ah[0], aHiB + ksOff);
            ldsm_x4(ah[1], aHiB + FSTRIDE + ksOff);
            ldsm_x4(al[0], aLoB + ksOff);
            ldsm_x4(al[1], aLoB + FSTRIDE + ksOff);
            #pragma unroll
            for (int j = 0; j < 8; j++) {
                uint32_t bh0, bh1, bl0, bl1;
                ldsm_x2(bh0, bh1, bHiB + j * JSTRIDE + ksOff);
                ldsm_x2(bl0, bl1, bLoB + j * JSTRIDE + ksOff);
                #pragma unroll
                for (int f = 0; f < 2; f++) {
                    mma_bf16(c[f][j], ah[f][0], ah[f][1], ah[f][2], ah[f][3], bh0, bh1);
                    mma_bf16(c[f][j], ah[f][0], ah[f][1], ah[f][2], ah[f][3], bl0, bl1);
                    mma_bf16(c[f][j], al[f][0], al[f][1], al[f][2], al[f][3], bh0, bh1);
                }
            }
        }
        __syncthreads();
    }

    #pragma unroll
    for (int f = 0; f < 2; f++) {
        int row0 = m0 + mbase + f * 16 + r;
        #pragma unroll
        for (int j = 0; j < 8; j++) {
            int col = n0 + nbase + j * 8 + 2 * tq;
            float2 bb = *(const float2*)&g_bias[col];
            float2 o0 = make_float2(c[f][j][0] + bb.x, c[f][j][1] + bb.y);
            float2 o1 = make_float2(c[f][j][2] + bb.x, c[f][j][3] + bb.y);
            __stcs((float2*)&g_xw[(size_t)row0 * GG + col], o0);
            __stcs((float2*)&g_xw[(size_t)(row0 + 8) * GG + col], o1);
        }
    }
}

// ---------------------------------------------------------------------------
// Persistent LSTM recurrence — restructured:
// Grid (32, 4), 512 threads = 16 warps. Block tile 32 rows x 64 gate-cols.
// NO K-split: each warp owns m16 x n8 over full K=512 (rowhalf = wid>>3,
// colg = wid&7). No partials smem, no reduction pass. Gates assembled
// in-register via two shfl_xor(1); each lane updates one (row, h-col).
// B hi+lo fetched with ONE ldmatrix.x4 (lanes 0-15 -> u_hi, 16-31 -> u_lo).
// ---------------------------------------------------------------------------
#define ROWW 260   // uint32 words per padded bf16 row (520 bf16; 256 data words)
__global__ __launch_bounds__(512) void lstm_persist(const float* __restrict__ c0,
                                                    float* __restrict__ out)
{
    extern __shared__ __align__(16) uint32_t smw[];
    uint32_t* u_hi = smw;                               // [64][260]
    uint32_t* u_lo = smw + 64 * ROWW;                   // [64][260]
    uint32_t* h_hi = smw + 2 * 64 * ROWW;               // [32][260]
    uint32_t* h_lo = smw + 2 * 64 * ROWW + 32 * ROWW;   // [32][260]

    const int tid = threadIdx.x;
    const int bx  = blockIdx.x;            // 0..31 col block
    const int rg  = blockIdx.y;            // 0..3  row group
    const int n0  = bx * 64;               // interleaved gate-col base
    const int b0  = rg * 32;               // batch row base

    const int lane = tid & 31;
    const int wid  = tid >> 5;             // 0..15
    const int rowhalf = wid >> 3;          // 0..1 -> rows 0-15 / 16-31
    const int colg    = wid & 7;           // 0..7 -> cols 8*colg..8*colg+7
    const int r  = lane >> 2;              // 0..7
    const int tq = lane & 3;               // 0..3

    // per-lane output element: one (batch row, h-col)
    const int row_local = rowhalf * 16 + r + ((tq & 1) << 3);
    const int j_local   = colg * 2 + (tq >> 1);
    const int jglob = bx * 16 + j_local;
    const int pidx  = (b0 + row_local) * HH + jglob;

    // ldmatrix per-lane base addresses (bytes)
    const uint32_t aOff = ((rowhalf * 16 + (lane & 15)) * ROWW + (lane >> 4) * 4) << 2;
    const uint32_t hHiB = smem_cast(h_hi) + aOff;
    const uint32_t hLoB = smem_cast(h_lo) + aOff;
    // B mixed hi/lo x4: lanes 0-15 address u_hi, lanes 16-31 address u_lo
    const uint32_t bOff = ((colg * 8 + (lane & 7)) * ROWW + ((lane >> 3) & 1) * 4) << 2;
    const uint32_t uB = smem_cast((lane < 16) ? u_hi : u_lo) + bOff;

    // ---- load persistent U'^T slice (bf16 hi/lo) ----
    #pragma unroll
    for (int q = 0; q < 8; q++) {
        int u = tid + q * 512;              // 0..4095
        int row = u >> 6;                   // 0..63
        int c4  = u & 63;
        uint4 vh = *((const uint4*)(g_UThi + (size_t)(n0 + row) * HH) + c4);
        uint4 vl = *((const uint4*)(g_UTlo + (size_t)(n0 + row) * HH) + c4);
        *(uint4*)(u_hi + row * ROWW + c4 * 4) = vh;
        *(uint4*)(u_lo + row * ROWW + c4 * 4) = vl;
    }

    float cr = c0[pidx];
    float mr = g_mdhp[pidx];
    __syncthreads();

    for (int t = 0; t < SS; t++) {
        // ---- stage h (bf16 hi/lo): 32 rows x 256 words, coalesced L2 reads ----
        const __nv_bfloat16* hbh = g_hBhi + (size_t)(t & 1) * (BB * HH);
        const __nv_bfloat16* hbl = g_hBlo + (size_t)(t & 1) * (BB * HH);
        #pragma unroll
        for (int q = 0; q < 4; q++) {
            int u = tid + q * 512;          // 0..2047
            int row = u >> 6;               // 0..31
            int c4  = u & 63;
            uint4 vh = __ldcg((const uint4*)(hbh + (size_t)(b0 + row) * HH) + c4);
            uint4 vl = __ldcg((const uint4*)(hbl + (size_t)(b0 + row) * HH) + c4);
            *(uint4*)(h_hi + row * ROWW + c4 * 4) = vh;
            *(uint4*)(h_lo + row * ROWW + c4 * 4) = vl;
        }
        float4 xw4 = __ldcs((const float4*)&g_xw[((size_t)t * BB + b0 + row_local) * GG
                                                 + n0 + j_local * 4]);
        __syncthreads();

        // ---- GEMM: warp tile m16 x n8, full K=512 (32 k-steps) ----
        float c[4] = {};
        #pragma unroll 8
        for (int ks = 0; ks < 32; ks++) {
            const uint32_t ksOff = ks * 32;   // 8 words = k16
            uint32_t ah[4], al[4], bb[4];
            ldsm_x4(ah, hHiB + ksOff);
            ldsm_x4(al, hLoB + ksOff);
            ldsm_x4(bb, uB + ksOff);          // bb[0..1]=B_hi, bb[2..3]=B_lo
            mma_bf16(c, ah[0], ah[1], ah[2], ah[3], bb[0], bb[1]);
            mma_bf16(c, ah[0], ah[1], ah[2], ah[3], bb[2], bb[3]);
            mma_bf16(c, al[0], al[1], al[2], al[3], bb[0], bb[1]);
        }

        // ---- in-register gate assembly: lane pairs exchange (i,f)<->(c,o) ----
        {
            float x = __shfl_xor_sync(0xffffffffu, (tq & 1) ? c[0] : c[2], 1);
            float y = __shfl_xor_sync(0xffffffffu, (tq & 1) ? c[1] : c[3], 1);
            float gi, gf, gc, go;
            if (tq & 1) { gi = x;    gf = y;    gc = c[2]; go = c[3]; }   // row r+8
            else        { gi = c[0]; gf = c[1]; gc = x;    go = y;    }   // row r
            gi += xw4.x; gf += xw4.y; gc += xw4.z; go += xw4.w;
            float it_ = 1.f / (1.f + __expf(-gi));
            float ft  = 1.f / (1.f + __expf(-gf));
            float ch  = tanhf(gc);
            float ot  = 1.f / (1.f + __expf(-go));
            float cn  = mr * (ft * cr + it_ * ch);
            cr = cn;
            float hn = ot * tanhf(cn);
            out[(size_t)t * BH + pidx] = hn;
            size_t nb = (size_t)((t + 1) & 1) * (BB * HH);
            __nv_bfloat16 hb = __float2bfloat16(hn);
            g_hBhi[nb + pidx] = hb;
            g_hBlo[nb + pidx] = __float2bfloat16(hn - __bfloat162float(hb));
        }

        // ---- per-rowgroup barrier (32 blocks) ----
        __syncthreads();
        if (tid == 0) {
            __threadfence();
            atomicAdd(&g_ctr4[rg], 1u);
            unsigned target = (unsigned)(t + 1) * 32u;
            while (*(volatile unsigned*)&g_ctr4[rg] < target) { }
            __threadfence();
        }
        __syncthreads();
    }

    g_c[pidx] = cr;
}

// copy h_T (== outputs[S-1]) and c_T into the output tail
__global__ void finalize(float* __restrict__ out)
{
    int i = blockIdx.x * blockDim.x + threadIdx.x;
    if (i < BH) {
        out[(size_t)SS * BH + i]      = out[(size_t)(SS - 1) * BH + i];
        out[(size_t)SS * BH + BH + i] = g_c[i];
    }
}

// ---------------------------------------------------------------------------
extern "C" void kernel_launch(void* const* d_in, const int* in_sizes, int n_in,
                              void* d_out, int out_size)
{
    const float* x     = (const float*)d_in[0];
    const float* h0    = (const float*)d_in[1];
    const float* c0    = (const float*)d_in[2];
    const float* alpha = (const float*)d_in[3];
    const float* beta  = (const float*)d_in[4];
    const float* theta = (const float*)d_in[5];
    const float* tspan = (const float*)d_in[6];
    const float* A     = (const float*)d_in[7];
    const float* Bm    = (const float*)d_in[8];
    const float* C     = (const float*)d_in[9];
    const float* Wi = (const float*)d_in[10];
    const float* Ui = (const float*)d_in[11];
    const float* bi = (const float*)d_in[12];
    const float* Wf = (const float*)d_in[13];
    const float* Uf = (const float*)d_in[14];
    const float* bf = (const float*)d_in[15];
    const float* Wc = (const float*)d_in[16];
    const float* Uc = (const float*)d_in[17];
    const float* bc = (const float*)d_in[18];
    const float* Wo = (const float*)d_in[19];
    const float* Uo = (const float*)d_in[20];
    const float* bo = (const float*)d_in[21];
    float* out = (float*)d_out;

    const int SMEM  = (2 * 64 * ROWW + 2 * 32 * ROWW) * 4;   // 199680 B
    const int XSMEM = 4 * 128 * ROWX * 4;                    // 73728 B
    cudaFuncSetAttribute(lstm_persist, cudaFuncAttributeMaxDynamicSharedMemorySize, SMEM);
    cudaFuncSetAttribute(xw_mma, cudaFuncAttributeMaxDynamicSharedMemorySize, XSMEM);

    prep_weights<<<1024, 256>>>(Wi, Ui, bi, Wf, Uf, bf, Wc, Uc, bc, Wo, Uo, bo);
    mdhp_kernel<<<BB, 512>>>(alpha, beta, theta, tspan, A, Bm, C);
    xsplit<<<(SS * BB * DD / 4) / 256, 256>>>(x);
    xw_mma<<<dim3(GG / 128, (SS * BB) / 128), 256, XSMEM>>>();
    prep_state<<<(BB * HH + 255) / 256, 256>>>(h0);
    lstm_persist<<<dim3(32, 4), 512, SMEM>>>(c0, out);
    finalize<<<(BH + 255) / 256, 256>>>(out);
}

// round 13
// speedup vs baseline: 1.1698x; 1.1698x over previous
#include <cuda_runtime.h>
#include <cuda_bf16.h>
#include <math.h>
#include <stdint.h>

// Problem dimensions (fixed by the dataset)
#define SS 512   // timesteps
#define BB 128   // batch
#define DD 256   // input dim
#define HH 512   // hidden
#define GG 2048  // 4*H (gate-interleaved: col n = j*4 + gate)
#define BH (BB*HH)

// Device scratch (no runtime allocation allowed)
__device__ float g_bias[GG];                 // interleaved bias [2048]
__device__ __nv_bfloat16 g_UThi[GG*HH];      // U'^T hi  [2048 n][512 k] bf16
__device__ __nv_bfloat16 g_UTlo[GG*HH];      // U'^T lo
__device__ __nv_bfloat16 g_WThi[GG*DD];      // W'^T hi  [2048 n][256 k] bf16
__device__ __nv_bfloat16 g_WTlo[GG*DD];      // W'^T lo
__device__ __nv_bfloat16 g_xhi[(size_t)SS*BB*DD];  // x hi  [65536 m][256 k] bf16
__device__ __nv_bfloat16 g_xlo[(size_t)SS*BB*DD];  // x lo
__device__ __nv_bfloat16 g_hBhi[2*BB*HH];    // double-buffered h hi [2][128 b][512 k]
__device__ __nv_bfloat16 g_hBlo[2*BB*HH];    // double-buffered h lo
__device__ float g_mdhp[BH];                 // tanh(alpha@A - (beta*ts)@B + theta@C)
__device__ float g_c[BH];                    // final cell state (for finalize)
__device__ float g_xw[(size_t)SS*BB*GG];     // precomputed x@W' + b  (512 MB)
__device__ unsigned g_ctr4[4];               // per-rowgroup barrier counters

// ---------------------------------------------------------------------------
// helpers
// ---------------------------------------------------------------------------
__device__ __forceinline__ void mma_bf16(float* c, uint32_t a0, uint32_t a1,
                                         uint32_t a2, uint32_t a3,
                                         uint32_t b0, uint32_t b1) {
    asm volatile("mma.sync.aligned.m16n8k16.row.col.f32.bf16.bf16.f32 "
        "{%0,%1,%2,%3}, {%4,%5,%6,%7}, {%8,%9}, {%0,%1,%2,%3};"
        : "+f"(c[0]), "+f"(c[1]), "+f"(c[2]), "+f"(c[3])
        : "r"(a0), "r"(a1), "r"(a2), "r"(a3), "r"(b0), "r"(b1));
}
__device__ __forceinline__ void ldsm_x4(uint32_t* r, uint32_t addr) {
    asm volatile("ldmatrix.sync.aligned.m8n8.x4.shared.b16 {%0,%1,%2,%3}, [%4];"
        : "=r"(r[0]), "=r"(r[1]), "=r"(r[2]), "=r"(r[3]) : "r"(addr));
}
__device__ __forceinline__ void ldsm_x2(uint32_t& r0, uint32_t& r1, uint32_t addr) {
    asm volatile("ldmatrix.sync.aligned.m8n8.x2.shared.b16 {%0,%1}, [%2];"
        : "=r"(r0), "=r"(r1) : "r"(addr));
}
__device__ __forceinline__ uint32_t smem_cast(const void* p) {
    return (uint32_t)__cvta_generic_to_shared(p);
}

// ---------------------------------------------------------------------------
// Build bf16-split U'^T, W'^T (both [n][k], n gate-interleaved), and bias.
// ---------------------------------------------------------------------------
__global__ void prep_weights(const float* __restrict__ Wi, const float* __restrict__ Ui, const float* __restrict__ bi,
                             const float* __restrict__ Wf, const float* __restrict__ Uf, const float* __restrict__ bf,
                             const float* __restrict__ Wc, const float* __restrict__ Uc, const float* __restrict__ bc,
                             const float* __restrict__ Wo, const float* __restrict__ Uo, const float* __restrict__ bo)
{
    int idx = blockIdx.x * blockDim.x + threadIdx.x;
    int stride = gridDim.x * blockDim.x;
    for (int i = idx; i < HH * GG; i += stride) {
        {   // U'^T bf16 hi/lo: i = n*512 + k
            int n = i >> 9, k = i & 511;
            int j = n >> 2, g = n & 3;
            const float* U = (g == 0) ? Ui : (g == 1) ? Uf : (g == 2) ? Uc : Uo;
            float u = U[k * HH + j];
            __nv_bfloat16 hi = __float2bfloat16(u);
            g_UThi[i] = hi;
            g_UTlo[i] = __float2bfloat16(u - __bfloat162float(hi));
        }
        if (i < GG * DD) {   // W'^T bf16 hi/lo: i = n*256 + k
            int n = i >> 8, k = i & 255;
            int j = n >> 2, g = n & 3;
            const float* W = (g == 0) ? Wi : (g == 1) ? Wf : (g == 2) ? Wc : Wo;
            float w = W[k * HH + j];
            __nv_bfloat16 hi = __float2bfloat16(w);
            g_WThi[i] = hi;
            g_WTlo[i] = __float2bfloat16(w - __bfloat162float(hi));
        }
        if (i < GG) {
            int j = i >> 2, g = i & 3;
            const float* bptr = (g == 0) ? bi : (g == 1) ? bf : (g == 2) ? bc : bo;
            g_bias[i] = bptr[j];
        }
    }
}

// split x into bf16 hi/lo (16.7M elements, 4 per thread)
__global__ void xsplit(const float* __restrict__ x)
{
    size_t i = (size_t)blockIdx.x * blockDim.x + threadIdx.x;   // float4 index
    float4 v = *((const float4*)x + i);
    __nv_bfloat16 h0 = __float2bfloat16(v.x);
    __nv_bfloat16 h1 = __float2bfloat16(v.y);
    __nv_bfloat16 h2 = __float2bfloat16(v.z);
    __nv_bfloat16 h3 = __float2bfloat16(v.w);
    __nv_bfloat16 l0 = __float2bfloat16(v.x - __bfloat162float(h0));
    __nv_bfloat16 l1 = __float2bfloat16(v.y - __bfloat162float(h1));
    __nv_bfloat16 l2 = __float2bfloat16(v.z - __bfloat162float(h2));
    __nv_bfloat16 l3 = __float2bfloat16(v.w - __bfloat162float(h3));
    ushort4 ph = make_ushort4(__bfloat16_as_ushort(h0), __bfloat16_as_ushort(h1),
                              __bfloat16_as_ushort(h2), __bfloat16_as_ushort(h3));
    ushort4 pl = make_ushort4(__bfloat16_as_ushort(l0), __bfloat16_as_ushort(l1),
                              __bfloat16_as_ushort(l2), __bfloat16_as_ushort(l3));
    *((ushort4*)g_xhi + i) = ph;
    *((ushort4*)g_xlo + i) = pl;
}

// ---------------------------------------------------------------------------
// mdhp = tanh(alpha @ A - (beta*tspan) @ B + theta @ C)   [B,H]
// ---------------------------------------------------------------------------
__global__ void mdhp_kernel(const float* __restrict__ alpha, const float* __restrict__ beta,
                            const float* __restrict__ theta, const float* __restrict__ tspan,
                            const float* __restrict__ A, const float* __restrict__ Bm,
                            const float* __restrict__ C)
{
    int b = blockIdx.x;
    int j = threadIdx.x;   // 0..511
    __shared__ float sa[256], sb[256], st[16];
    float ts = tspan[b];
    if (j < 256) {
        sa[j] = alpha[b * 256 + j];
        sb[j] = beta[b * 256 + j] * ts;
    }
    if (j < 16) st[j] = theta[b * 16 + j];
    __syncthreads();
    float acc = 0.f;
    #pragma unroll 4
    for (int k = 0; k < 256; k++)
        acc += sa[k] * A[k * 512 + j] - sb[k] * Bm[k * 512 + j];
    #pragma unroll
    for (int k = 0; k < 16; k++)
        acc += st[k] * C[k * 512 + j];
    g_mdhp[b * 512 + j] = tanhf(acc);
}

// zero barrier counters + bf16-split h0 into g_hB buffer 0
__global__ void prep_state(const float* __restrict__ h0)
{
    int i = blockIdx.x * blockDim.x + threadIdx.x;
    if (i < 4) g_ctr4[i] = 0u;
    if (i < BB * HH) {
        float v = h0[i];                       // i = b*512 + k
        __nv_bfloat16 hi = __float2bfloat16(v);
        g_hBhi[i] = hi;
        g_hBlo[i] = __float2bfloat16(v - __bfloat162float(hi));
    }
}

// ---------------------------------------------------------------------------
// xW GEMM on mma.sync bf16 (2-way split, 3-term product) with ldmatrix:
//   g_xw[65536, 2048] = x[65536, 256] @ W'[256, 2048] + bias
// Block: 128x128 C tile, 256 threads = 8 warps (4 M x 2 N), warp tile 32x64.
// (byte-identical to round 11 — measured 623us, tensor=54.5%)
// ---------------------------------------------------------------------------
#define ROWX 36   // uint32 words per padded row (32 data words = 64 bf16)
__global__ __launch_bounds__(256, 2) void xw_mma()
{
    extern __shared__ __align__(16) uint32_t xs[];
    uint32_t* a_hi = xs;                    // [128][36]
    uint32_t* a_lo = xs + 128 * ROWX;
    uint32_t* b_hi = xs + 2 * 128 * ROWX;
    uint32_t* b_lo = xs + 3 * 128 * ROWX;

    const int tid  = threadIdx.x;
    const int lane = tid & 31;
    const int wid  = tid >> 5;
    const int mbase = (wid & 3) * 32;       // 0,32,64,96
    const int nbase = (wid >> 2) * 64;      // 0,64
    const int r  = lane >> 2;               // 0..7
    const int tq = lane & 3;                // 0..3
    const int n0 = blockIdx.x * 128;
    const int m0 = blockIdx.y * 128;

    const uint32_t aRowOff = ((mbase + (lane & 15)) * ROWX + (lane >> 4) * 4) << 2;
    const uint32_t aHiB = smem_cast(a_hi) + aRowOff;
    const uint32_t aLoB = smem_cast(a_lo) + aRowOff;
    const uint32_t bRowOff = ((nbase + (lane & 7)) * ROWX + ((lane >> 3) & 1) * 4) << 2;
    const uint32_t bHiB = smem_cast(b_hi) + bRowOff;
    const uint32_t bLoB = smem_cast(b_lo) + bRowOff;
    const uint32_t FSTRIDE = (16 * ROWX) << 2;   // f: +16 rows
    const uint32_t JSTRIDE = (8 * ROWX) << 2;    // j: +8 rows

    float c[2][8][4];
    #pragma unroll
    for (int f = 0; f < 2; f++)
        #pragma unroll
        for (int j = 0; j < 8; j++)
            #pragma unroll
            for (int q = 0; q < 4; q++) c[f][j][q] = 0.f;

    for (int kc = 0; kc < 4; kc++) {
        const int k0 = kc * 64;
        #pragma unroll
        for (int q = 0; q < 4; q++) {
            int u = tid + q * 256;          // 0..1023
            int row = u >> 3;               // 0..127
            int c4  = u & 7;                // uint4 within row
            uint4 vah = *((const uint4*)(g_xhi + (size_t)(m0 + row) * DD + k0) + c4);
            uint4 val = *((const uint4*)(g_xlo + (size_t)(m0 + row) * DD + k0) + c4);
            uint4 vbh = *((const uint4*)(g_WThi + (size_t)(n0 + row) * DD + k0) + c4);
            uint4 vbl = *((const uint4*)(g_WTlo + (size_t)(n0 + row) * DD + k0) + c4);
            *(uint4*)(a_hi + row * ROWX + c4 * 4) = vah;
            *(uint4*)(a_lo + row * ROWX + c4 * 4) = val;
            *(uint4*)(b_hi + row * ROWX + c4 * 4) = vbh;
            *(uint4*)(b_lo + row * ROWX + c4 * 4) = vbl;
        }
        __syncthreads();

        #pragma unroll
        for (int ks = 0; ks < 4; ks++) {
            const uint32_t ksOff = ks * 32;          // 8 words
            uint32_t ah[2][4], al[2][4];
            ldsm_x4(ah[0], aHiB + ksOff);
            ldsm_x4(ah[1], aHiB + FSTRIDE + ksOff);
            ldsm_x4(al[0], aLoB + ksOff);
            ldsm_x4(al[1], aLoB + FSTRIDE + ksOff);
            #pragma unroll
            for (int j = 0; j < 8; j++) {
                uint32_t bh0, bh1, bl0, bl1;
                ldsm_x2(bh0, bh1, bHiB + j * JSTRIDE + ksOff);
                ldsm_x2(bl0, bl1, bLoB + j * JSTRIDE + ksOff);
                #pragma unroll
                for (int f = 0; f < 2; f++) {
                    mma_bf16(c[f][j], ah[f][0], ah[f][1], ah[f][2], ah[f][3], bh0, bh1);
                    mma_bf16(c[f][j], ah[f][0], ah[f][1], ah[f][2], ah[f][3], bl0, bl1);
                    mma_bf16(c[f][j], al[f][0], al[f][1], al[f][2], al[f][3], bh0, bh1);
                }
            }
        }
        __syncthreads();
    }

    #pragma unroll
    for (int f = 0; f < 2; f++) {
        int row0 = m0 + mbase + f * 16 + r;
        #pragma unroll
        for (int j = 0; j < 8; j++) {
            int col = n0 + nbase + j * 8 + 2 * tq;
            float2 bb = *(const float2*)&g_bias[col];
            float2 o0 = make_float2(c[f][j][0] + bb.x, c[f][j][1] + bb.y);
            float2 o1 = make_float2(c[f][j][2] + bb.x, c[f][j][3] + bb.y);
            __stcs((float2*)&g_xw[(size_t)row0 * GG + col], o0);
            __stcs((float2*)&g_xw[(size_t)(row0 + 8) * GG + col], o1);
        }
    }
}

// ---------------------------------------------------------------------------
// Persistent LSTM recurrence on mma.sync bf16 — byte-identical to round 8
// (the best-measured recurrence: plain LDS fragment loads, 2-way K-split,
// smem partial reduction, ~3.1us/step).
// ---------------------------------------------------------------------------
#define ROWW 260   // uint32 words per padded bf16 row (520 bf16; 256 data words)
__global__ __launch_bounds__(512) void lstm_persist(const float* __restrict__ c0,
                                                    float* __restrict__ out)
{
    extern __shared__ __align__(16) uint32_t smw[];
    uint32_t* u_hi = smw;                               // [64][260]
    uint32_t* u_lo = smw + 64 * ROWW;                   // [64][260]
    uint32_t* h_hi = smw + 2 * 64 * ROWW;               // [32][260]
    uint32_t* h_lo = smw + 2 * 64 * ROWW + 32 * ROWW;   // [32][260]
    float*    part = (float*)(smw + 2 * 64 * ROWW + 2 * 32 * ROWW); // [2][32][68]

    const int tid = threadIdx.x;
    const int bx  = blockIdx.x;            // 0..31 col block
    const int rg  = blockIdx.y;            // 0..3  row group
    const int n0  = bx * 64;               // interleaved gate-col base
    const int b0  = rg * 32;               // batch row base

    const int lane = tid & 31;
    const int wid  = tid >> 5;             // 0..15
    const int kseg  = wid >> 3;            // 0..1  K half
    const int ow    = wid & 7;             // 0..7  output warp
    const int mbase = (ow >> 2) * 16;      // 0 or 16
    const int nbase = (ow & 3) * 16;       // 0,16,32,48
    const int r  = lane >> 2;              // 0..7
    const int tq = lane & 3;               // 0..3

    const int pr = tid >> 4;               // 0..31
    const int pj = tid & 15;               // 0..15
    const int jglob = bx * 16 + pj;
    const int pidx = (b0 + pr) * HH + jglob;

    // ---- load persistent U'^T slice (bf16 hi/lo) ----
    #pragma unroll
    for (int q = 0; q < 8; q++) {
        int u = tid + q * 512;              // 0..4095
        int row = u >> 6;                   // 0..63
        int c4  = u & 63;
        uint4 vh = *((const uint4*)(g_UThi + (size_t)(n0 + row) * HH) + c4);
        uint4 vl = *((const uint4*)(g_UTlo + (size_t)(n0 + row) * HH) + c4);
        *(uint4*)(u_hi + row * ROWW + c4 * 4) = vh;
        *(uint4*)(u_lo + row * ROWW + c4 * 4) = vl;
    }

    float cr = c0[pidx];
    float mr = g_mdhp[pidx];
    __syncthreads();

    for (int t = 0; t < SS; t++) {
        const __nv_bfloat16* hbh = g_hBhi + (size_t)(t & 1) * (BB * HH);
        const __nv_bfloat16* hbl = g_hBlo + (size_t)(t & 1) * (BB * HH);
        #pragma unroll
        for (int q = 0; q < 4; q++) {
            int u = tid + q * 512;          // 0..2047
            int row = u >> 6;               // 0..31
            int c4  = u & 63;
            uint4 vh = __ldcg((const uint4*)(hbh + (size_t)(b0 + row) * HH) + c4);
            uint4 vl = __ldcg((const uint4*)(hbl + (size_t)(b0 + row) * HH) + c4);
            *(uint4*)(h_hi + row * ROWW + c4 * 4) = vh;
            *(uint4*)(h_lo + row * ROWW + c4 * 4) = vl;
        }
        float4 xw4 = *(const float4*)&g_xw[((size_t)t * BB + b0 + pr) * GG + n0 + pj * 4];
        __syncthreads();

        float c[2][4] = {};
        const int arow0 = (mbase + r) * ROWW;
        const int arow1 = (mbase + r + 8) * ROWW;
        #pragma unroll 4
        for (int ks = 0; ks < 16; ks++) {
            int kw = kseg * 128 + ks * 8 + tq;
            uint32_t ah0 = h_hi[arow0 + kw];
            uint32_t ah1 = h_hi[arow1 + kw];
            uint32_t ah2 = h_hi[arow0 + kw + 4];
            uint32_t ah3 = h_hi[arow1 + kw + 4];
            uint32_t al0 = h_lo[arow0 + kw];
            uint32_t al1 = h_lo[arow1 + kw];
            uint32_t al2 = h_lo[arow0 + kw + 4];
            uint32_t al3 = h_lo[arow1 + kw + 4];
            #pragma unroll
            for (int j = 0; j < 2; j++) {
                int nr = (nbase + j * 8 + r) * ROWW + kw;
                uint32_t bh0 = u_hi[nr], bh1 = u_hi[nr + 4];
                uint32_t bl0 = u_lo[nr], bl1 = u_lo[nr + 4];
                mma_bf16(c[j], ah0, ah1, ah2, ah3, bh0, bh1);
                mma_bf16(c[j], ah0, ah1, ah2, ah3, bl0, bl1);
                mma_bf16(c[j], al0, al1, al2, al3, bh0, bh1);
            }
        }

        #pragma unroll
        for (int j = 0; j < 2; j++) {
            float* p = part + kseg * (32 * 68) + (mbase + r) * 68 + nbase + j * 8 + 2 * tq;
            *(float2*)p            = make_float2(c[j][0], c[j][1]);
            *(float2*)(p + 8 * 68) = make_float2(c[j][2], c[j][3]);
        }
        __syncthreads();

        {
            float4 p0 = *(const float4*)&part[pr * 68 + pj * 4];
            float4 p1 = *(const float4*)&part[32 * 68 + pr * 68 + pj * 4];
            float gi = p0.x + p1.x + xw4.x;
            float gf = p0.y + p1.y + xw4.y;
            float gc = p0.z + p1.z + xw4.z;
            float go = p0.w + p1.w + xw4.w;
            float it_ = 1.f / (1.f + __expf(-gi));
            float ft  = 1.f / (1.f + __expf(-gf));
            float ch  = tanhf(gc);
            float ot  = 1.f / (1.f + __expf(-go));
            float cn  = mr * (ft * cr + it_ * ch);
            cr = cn;
            float hn = ot * tanhf(cn);
            out[(size_t)t * BH + pidx] = hn;
            size_t nb = (size_t)((t + 1) & 1) * (BB * HH);
            __nv_bfloat16 hb = __float2bfloat16(hn);
            g_hBhi[nb + pidx] = hb;
            g_hBlo[nb + pidx] = __float2bfloat16(hn - __bfloat162float(hb));
        }

        __syncthreads();
        if (tid == 0) {
            __threadfence();
            atomicAdd(&g_ctr4[rg], 1u);
            unsigned target = (unsigned)(t + 1) * 32u;
            while (*(volatile unsigned*)&g_ctr4[rg] < target) { }
            __threadfence();
        }
        __syncthreads();
    }

    g_c[pidx] = cr;
}

// copy h_T (== outputs[S-1]) and c_T into the output tail
__global__ void finalize(float* __restrict__ out)
{
    int i = blockIdx.x * blockDim.x + threadIdx.x;
    if (i < BH) {
        out[(size_t)SS * BH + i]      = out[(size_t)(SS - 1) * BH + i];
        out[(size_t)SS * BH + BH + i] = g_c[i];
    }
}

// ---------------------------------------------------------------------------
extern "C" void kernel_launch(void* const* d_in, const int* in_sizes, int n_in,
                              void* d_out, int out_size)
{
    const float* x     = (const float*)d_in[0];
    const float* h0    = (const float*)d_in[1];
    const float* c0    = (const float*)d_in[2];
    const float* alpha = (const float*)d_in[3];
    const float* beta  = (const float*)d_in[4];
    const float* theta = (const float*)d_in[5];
    const float* tspan = (const float*)d_in[6];
    const float* A     = (const float*)d_in[7];
    const float* Bm    = (const float*)d_in[8];
    const float* C     = (const float*)d_in[9];
    const float* Wi = (const float*)d_in[10];
    const float* Ui = (const float*)d_in[11];
    const float* bi = (const float*)d_in[12];
    const float* Wf = (const float*)d_in[13];
    const float* Uf = (const float*)d_in[14];
    const float* bf = (const float*)d_in[15];
    const float* Wc = (const float*)d_in[16];
    const float* Uc = (const float*)d_in[17];
    const float* bc = (const float*)d_in[18];
    const float* Wo = (const float*)d_in[19];
    const float* Uo = (const float*)d_in[20];
    const float* bo = (const float*)d_in[21];
    float* out = (float*)d_out;

    const int SMEM  = (2 * 64 * ROWW + 2 * 32 * ROWW + 2 * 32 * 68) * 4;  // 217088 B
    const int XSMEM = 4 * 128 * ROWX * 4;                                  // 73728 B
    cudaFuncSetAttribute(lstm_persist, cudaFuncAttributeMaxDynamicSharedMemorySize, SMEM);
    cudaFuncSetAttribute(xw_mma, cudaFuncAttributeMaxDynamicSharedMemorySize, XSMEM);

    prep_weights<<<1024, 256>>>(Wi, Ui, bi, Wf, Uf, bf, Wc, Uc, bc, Wo, Uo, bo);
    mdhp_kernel<<<BB, 512>>>(alpha, beta, theta, tspan, A, Bm, C);
    xsplit<<<(SS * BB * DD / 4) / 256, 256>>>(x);
    xw_mma<<<dim3(GG / 128, (SS * BB) / 128), 256, XSMEM>>>();
    prep_state<<<(BB * HH + 255) / 256, 256>>>(h0);
    lstm_persist<<<dim3(32, 4), 512, SMEM>>>(c0, out);
    finalize<<<(BH + 255) / 256, 256>>>(out);
}

// round 14
// speedup vs baseline: 1.2269x; 1.0488x over previous
#include <cuda_runtime.h>
#include <cuda_bf16.h>
#include <math.h>
#include <stdint.h>

// Problem dimensions (fixed by the dataset)
#define SS 512   // timesteps
#define BB 128   // batch
#define DD 256   // input dim
#define HH 512   // hidden
#define GG 2048  // 4*H (gate-interleaved: col n = j*4 + gate)
#define BH (BB*HH)

// Device scratch (no runtime allocation allowed)
__device__ float g_bias[GG];                 // interleaved bias [2048]
__device__ __nv_bfloat16 g_UThi[GG*HH];      // U'^T hi  [2048 n][512 k] bf16
__device__ __nv_bfloat16 g_UTlo[GG*HH];      // U'^T lo
__device__ __nv_bfloat16 g_WThi[GG*DD];      // W'^T hi  [2048 n][256 k] bf16
__device__ __nv_bfloat16 g_WTlo[GG*DD];      // W'^T lo
__device__ __nv_bfloat16 g_xhi[(size_t)SS*BB*DD];  // x hi  [65536 m][256 k] bf16
__device__ __nv_bfloat16 g_xlo[(size_t)SS*BB*DD];  // x lo
__device__ __nv_bfloat16 g_hBhi[2*BB*HH];    // double-buffered h hi [2][128 b][512 k]
__device__ __nv_bfloat16 g_hBlo[2*BB*HH];    // double-buffered h lo
__device__ float g_mdhp[BH];                 // tanh(alpha@A - (beta*ts)@B + theta@C)
__device__ float g_c[BH];                    // final cell state (for finalize)
__device__ float g_xw[(size_t)SS*BB*GG];     // precomputed x@W' + b  (512 MB)
__device__ unsigned g_ctr4[4];               // per-rowgroup barrier counters

// ---------------------------------------------------------------------------
// helpers
// ---------------------------------------------------------------------------
__device__ __forceinline__ void mma_bf16(float* c, uint32_t a0, uint32_t a1,
                                         uint32_t a2, uint32_t a3,
                                         uint32_t b0, uint32_t b1) {
    asm volatile("mma.sync.aligned.m16n8k16.row.col.f32.bf16.bf16.f32 "
        "{%0,%1,%2,%3}, {%4,%5,%6,%7}, {%8,%9}, {%0,%1,%2,%3};"
        : "+f"(c[0]), "+f"(c[1]), "+f"(c[2]), "+f"(c[3])
        : "r"(a0), "r"(a1), "r"(a2), "r"(a3), "r"(b0), "r"(b1));
}
__device__ __forceinline__ void ldsm_x4(uint32_t* r, uint32_t addr) {
    asm volatile("ldmatrix.sync.aligned.m8n8.x4.shared.b16 {%0,%1,%2,%3}, [%4];"
        : "=r"(r[0]), "=r"(r[1]), "=r"(r[2]), "=r"(r[3]) : "r"(addr));
}
__device__ __forceinline__ void ldsm_x2(uint32_t& r0, uint32_t& r1, uint32_t addr) {
    asm volatile("ldmatrix.sync.aligned.m8n8.x2.shared.b16 {%0,%1}, [%2];"
        : "=r"(r0), "=r"(r1) : "r"(addr));
}
__device__ __forceinline__ uint32_t smem_cast(const void* p) {
    return (uint32_t)__cvta_generic_to_shared(p);
}
__device__ __forceinline__ void cp16(uint32_t saddr, const void* g) {
    asm volatile("cp.async.ca.shared.global [%0], [%1], 16;" :: "r"(saddr), "l"(g));
}
#define CP_COMMIT() asm volatile("cp.async.commit_group;" ::: "memory")
#define CP_WAIT(n)  asm volatile("cp.async.wait_group %0;" :: "n"(n) : "memory")

// ---------------------------------------------------------------------------
// prep_U: tile-transpose U_g[512 k][512 j] -> g_UT{hi,lo}[n=4j+g][k], coalesced.
// grid (16 jt, 16 kt, 4 g), block (32, 8)
// ---------------------------------------------------------------------------
__global__ void prep_U(const float* __restrict__ Ui, const float* __restrict__ Uf,
                       const float* __restrict__ Uc, const float* __restrict__ Uo)
{
    __shared__ float tile[32][33];
    const int g = blockIdx.z;
    const float* U = (g == 0) ? Ui : (g == 1) ? Uf : (g == 2) ? Uc : Uo;
    const int j0 = blockIdx.x * 32, k0 = blockIdx.y * 32;
    const int tx = threadIdx.x, ty = threadIdx.y;
    #pragma unroll
    for (int q = 0; q < 4; q++) {
        int kk = ty + q * 8;
        tile[kk][tx] = U[(size_t)(k0 + kk) * HH + j0 + tx];
    }
    __syncthreads();
    #pragma unroll
    for (int q = 0; q < 4; q++) {
        int jj = ty + q * 8;
        float u = tile[tx][jj];                 // = U[k0+tx][j0+jj]
        __nv_bfloat16 hi = __float2bfloat16(u);
        size_t o = (size_t)(4 * (j0 + jj) + g) * HH + k0 + tx;
        g_UThi[o] = hi;
        g_UTlo[o] = __float2bfloat16(u - __bfloat162float(hi));
    }
}

// prep_W: same for W_g[256 k][512 j] -> g_WT{hi,lo}[n][k]. grid (16 jt, 8 kt, 4 g)
__global__ void prep_W(const float* __restrict__ Wi, const float* __restrict__ Wf,
                       const float* __restrict__ Wc, const float* __restrict__ Wo)
{
    __shared__ float tile[32][33];
    const int g = blockIdx.z;
    const float* W = (g == 0) ? Wi : (g == 1) ? Wf : (g == 2) ? Wc : Wo;
    const int j0 = blockIdx.x * 32, k0 = blockIdx.y * 32;
    const int tx = threadIdx.x, ty = threadIdx.y;
    #pragma unroll
    for (int q = 0; q < 4; q++) {
        int kk = ty + q * 8;
        tile[kk][tx] = W[(size_t)(k0 + kk) * HH + j0 + tx];
    }
    __syncthreads();
    #pragma unroll
    for (int q = 0; q < 4; q++) {
        int jj = ty + q * 8;
        float w = tile[tx][jj];
        __nv_bfloat16 hi = __float2bfloat16(w);
        size_t o = (size_t)(4 * (j0 + jj) + g) * DD + k0 + tx;
        g_WThi[o] = hi;
        g_WTlo[o] = __float2bfloat16(w - __bfloat162float(hi));
    }
}

// split x into bf16 hi/lo (16.7M elements, 4 per thread)
__global__ void xsplit(const float* __restrict__ x)
{
    size_t i = (size_t)blockIdx.x * blockDim.x + threadIdx.x;   // float4 index
    float4 v = *((const float4*)x + i);
    __nv_bfloat16 h0 = __float2bfloat16(v.x);
    __nv_bfloat16 h1 = __float2bfloat16(v.y);
    __nv_bfloat16 h2 = __float2bfloat16(v.z);
    __nv_bfloat16 h3 = __float2bfloat16(v.w);
    __nv_bfloat16 l0 = __float2bfloat16(v.x - __bfloat162float(h0));
    __nv_bfloat16 l1 = __float2bfloat16(v.y - __bfloat162float(h1));
    __nv_bfloat16 l2 = __float2bfloat16(v.z - __bfloat162float(h2));
    __nv_bfloat16 l3 = __float2bfloat16(v.w - __bfloat162float(h3));
    ushort4 ph = make_ushort4(__bfloat16_as_ushort(h0), __bfloat16_as_ushort(h1),
                              __bfloat16_as_ushort(h2), __bfloat16_as_ushort(h3));
    ushort4 pl = make_ushort4(__bfloat16_as_ushort(l0), __bfloat16_as_ushort(l1),
                              __bfloat16_as_ushort(l2), __bfloat16_as_ushort(l3));
    *((ushort4*)g_xhi + i) = ph;
    *((ushort4*)g_xlo + i) = pl;
}

// ---------------------------------------------------------------------------
// mdhp = tanh(alpha @ A - (beta*tspan) @ B + theta @ C)   [B,H]
// ---------------------------------------------------------------------------
__global__ void mdhp_kernel(const float* __restrict__ alpha, const float* __restrict__ beta,
                            const float* __restrict__ theta, const float* __restrict__ tspan,
                            const float* __restrict__ A, const float* __restrict__ Bm,
                            const float* __restrict__ C)
{
    int b = blockIdx.x;
    int j = threadIdx.x;   // 0..511
    __shared__ float sa[256], sb[256], st[16];
    float ts = tspan[b];
    if (j < 256) {
        sa[j] = alpha[b * 256 + j];
        sb[j] = beta[b * 256 + j] * ts;
    }
    if (j < 16) st[j] = theta[b * 16 + j];
    __syncthreads();
    float acc = 0.f;
    #pragma unroll 4
    for (int k = 0; k < 256; k++)
        acc += sa[k] * A[k * 512 + j] - sb[k] * Bm[k * 512 + j];
    #pragma unroll
    for (int k = 0; k < 16; k++)
        acc += st[k] * C[k * 512 + j];
    g_mdhp[b * 512 + j] = tanhf(acc);
}

// zero barrier counters + bf16-split h0 + interleaved bias
__global__ void prep_state(const float* __restrict__ h0,
                           const float* __restrict__ bi, const float* __restrict__ bf,
                           const float* __restrict__ bc, const float* __restrict__ bo)
{
    int i = blockIdx.x * blockDim.x + threadIdx.x;
    if (i < 4) g_ctr4[i] = 0u;
    if (i < GG) {
        int j = i >> 2, g = i & 3;
        const float* bptr = (g == 0) ? bi : (g == 1) ? bf : (g == 2) ? bc : bo;
        g_bias[i] = bptr[j];
    }
    if (i < BB * HH) {
        float v = h0[i];                       // i = b*512 + k
        __nv_bfloat16 hi = __float2bfloat16(v);
        g_hBhi[i] = hi;
        g_hBlo[i] = __float2bfloat16(v - __bfloat162float(hi));
    }
}

// ---------------------------------------------------------------------------
// xW GEMM on mma.sync bf16 (2-way split, 3-term product), ldmatrix loads,
// cp.async double-buffered stages (2 x 73728 B), occupancy 1.
//   g_xw[65536, 2048] = x[65536, 256] @ W'[256, 2048] + bias
// Block: 128x128 C tile, 256 threads = 8 warps (4 M x 2 N), warp tile 32x64.
// ---------------------------------------------------------------------------
#define ROWX 36                 // uint32 words per padded row (32 data words)
#define STGW (4 * 128 * ROWX)   // words per stage (a_hi,a_lo,b_hi,b_lo)
__global__ __launch_bounds__(256, 1) void xw_mma()
{
    extern __shared__ __align__(16) uint32_t xs[];

    const int tid  = threadIdx.x;
    const int lane = tid & 31;
    const int wid  = tid >> 5;
    const int mbase = (wid & 3) * 32;       // 0,32,64,96
    const int nbase = (wid >> 2) * 64;      // 0,64
    const int r  = lane >> 2;               // 0..7
    const int tq = lane & 3;                // 0..3
    const int n0 = blockIdx.x * 128;
    const int m0 = blockIdx.y * 128;

    const uint32_t smBase = smem_cast(xs);
    const uint32_t STGB = STGW * 4;                 // stage bytes
    const uint32_t ARRB = 128 * ROWX * 4;           // array bytes

    // ldmatrix per-lane base addresses (stage 0)
    const uint32_t aRowOff = ((mbase + (lane & 15)) * ROWX + (lane >> 4) * 4) << 2;
    const uint32_t aHiB = smBase + aRowOff;
    const uint32_t aLoB = smBase + ARRB + aRowOff;
    const uint32_t bRowOff = ((nbase + (lane & 7)) * ROWX + ((lane >> 3) & 1) * 4) << 2;
    const uint32_t bHiB = smBase + 2 * ARRB + bRowOff;
    const uint32_t bLoB = smBase + 3 * ARRB + bRowOff;
    const uint32_t FSTRIDE = (16 * ROWX) << 2;   // f: +16 rows
    const uint32_t JSTRIDE = (8 * ROWX) << 2;    // j: +8 rows

    // loader mapping: 4 q-iterations x 4 arrays, 16B each
    const int lrow = tid >> 3;           // reused with +q*32 rows? no: u = tid + q*256
    (void)lrow;

    float c[2][8][4];
    #pragma unroll
    for (int f = 0; f < 2; f++)
        #pragma unroll
        for (int j = 0; j < 8; j++)
            #pragma unroll
            for (int q = 0; q < 4; q++) c[f][j][q] = 0.f;

    // stage loader (cp.async)
    auto load_stage = [&](int s, int kc) {
        const int k0 = kc * 64;
        const uint32_t sb = smBase + s * STGB;
        #pragma unroll
        for (int q = 0; q < 4; q++) {
            int u = tid + q * 256;          // 0..1023
            int row = u >> 3;               // 0..127
            int c4  = u & 7;
            uint32_t so = (row * ROWX + c4 * 4) << 2;
            cp16(sb + so,            (const void*)((const uint4*)(g_xhi  + (size_t)(m0 + row) * DD + k0) + c4));
            cp16(sb + ARRB + so,     (const void*)((const uint4*)(g_xlo  + (size_t)(m0 + row) * DD + k0) + c4));
            cp16(sb + 2 * ARRB + so, (const void*)((const uint4*)(g_WThi + (size_t)(n0 + row) * DD + k0) + c4));
            cp16(sb + 3 * ARRB + so, (const void*)((const uint4*)(g_WTlo + (size_t)(n0 + row) * DD + k0) + c4));
        }
    };

    load_stage(0, 0);
    CP_COMMIT();

    for (int kc = 0; kc < 4; kc++) {
        if (kc < 3) {
            load_stage((kc + 1) & 1, kc + 1);
            CP_COMMIT();
            CP_WAIT(1);
        } else {
            CP_WAIT(0);
        }
        __syncthreads();

        const uint32_t so = (kc & 1) * STGB;
        #pragma unroll
        for (int ks = 0; ks < 4; ks++) {
            const uint32_t ksOff = so + ks * 32;
            uint32_t ah[2][4], al[2][4];
            ldsm_x4(ah[0], aHiB + ksOff);
            ldsm_x4(ah[1], aHiB + FSTRIDE + ksOff);
            ldsm_x4(al[0], aLoB + ksOff);
            ldsm_x4(al[1], aLoB + FSTRIDE + ksOff);
            #pragma unroll
            for (int j = 0; j < 8; j++) {
                uint32_t bh0, bh1, bl0, bl1;
                ldsm_x2(bh0, bh1, bHiB + j * JSTRIDE + ksOff);
                ldsm_x2(bl0, bl1, bLoB + j * JSTRIDE + ksOff);
                #pragma unroll
                for (int f = 0; f < 2; f++) {
                    mma_bf16(c[f][j], ah[f][0], ah[f][1], ah[f][2], ah[f][3], bh0, bh1);
                    mma_bf16(c[f][j], ah[f][0], ah[f][1], ah[f][2], ah[f][3], bl0, bl1);
                    mma_bf16(c[f][j], al[f][0], al[f][1], al[f][2], al[f][3], bh0, bh1);
                }
            }
        }
        __syncthreads();
    }

    #pragma unroll
    for (int f = 0; f < 2; f++) {
        int row0 = m0 + mbase + f * 16 + r;
        #pragma unroll
        for (int j = 0; j < 8; j++) {
            int col = n0 + nbase + j * 8 + 2 * tq;
            float2 bb = *(const float2*)&g_bias[col];
            float2 o0 = make_float2(c[f][j][0] + bb.x, c[f][j][1] + bb.y);
            float2 o1 = make_float2(c[f][j][2] + bb.x, c[f][j][3] + bb.y);
            __stcs((float2*)&g_xw[(size_t)row0 * GG + col], o0);
            __stcs((float2*)&g_xw[(size_t)(row0 + 8) * GG + col], o1);
        }
    }
}

// ---------------------------------------------------------------------------
// Persistent LSTM recurrence on mma.sync bf16 — r8 structure (proven),
// barrier switched to release/acquire atomics (no full membar).
// ---------------------------------------------------------------------------
#define ROWW 260   // uint32 words per padded bf16 row (520 bf16; 256 data words)
__global__ __launch_bounds__(512) void lstm_persist(const float* __restrict__ c0,
                                                    float* __restrict__ out)
{
    extern __shared__ __align__(16) uint32_t smw[];
    uint32_t* u_hi = smw;                               // [64][260]
    uint32_t* u_lo = smw + 64 * ROWW;                   // [64][260]
    uint32_t* h_hi = smw + 2 * 64 * ROWW;               // [32][260]
    uint32_t* h_lo = smw + 2 * 64 * ROWW + 32 * ROWW;   // [32][260]
    float*    part = (float*)(smw + 2 * 64 * ROWW + 2 * 32 * ROWW); // [2][32][68]

    const int tid = threadIdx.x;
    const int bx  = blockIdx.x;            // 0..31 col block
    const int rg  = blockIdx.y;            // 0..3  row group
    const int n0  = bx * 64;               // interleaved gate-col base
    const int b0  = rg * 32;               // batch row base

    const int lane = tid & 31;
    const int wid  = tid >> 5;             // 0..15
    const int kseg  = wid >> 3;            // 0..1  K half
    const int ow    = wid & 7;             // 0..7  output warp
    const int mbase = (ow >> 2) * 16;      // 0 or 16
    const int nbase = (ow & 3) * 16;       // 0,16,32,48
    const int r  = lane >> 2;              // 0..7
    const int tq = lane & 3;               // 0..3

    const int pr = tid >> 4;               // 0..31
    const int pj = tid & 15;               // 0..15
    const int jglob = bx * 16 + pj;
    const int pidx = (b0 + pr) * HH + jglob;

    // ---- load persistent U'^T slice (bf16 hi/lo) ----
    #pragma unroll
    for (int q = 0; q < 8; q++) {
        int u = tid + q * 512;              // 0..4095
        int row = u >> 6;                   // 0..63
        int c4  = u & 63;
        uint4 vh = *((const uint4*)(g_UThi + (size_t)(n0 + row) * HH) + c4);
        uint4 vl = *((const uint4*)(g_UTlo + (size_t)(n0 + row) * HH) + c4);
        *(uint4*)(u_hi + row * ROWW + c4 * 4) = vh;
        *(uint4*)(u_lo + row * ROWW + c4 * 4) = vl;
    }

    float cr = c0[pidx];
    float mr = g_mdhp[pidx];
    __syncthreads();

    for (int t = 0; t < SS; t++) {
        const __nv_bfloat16* hbh = g_hBhi + (size_t)(t & 1) * (BB * HH);
        const __nv_bfloat16* hbl = g_hBlo + (size_t)(t & 1) * (BB * HH);
        #pragma unroll
        for (int q = 0; q < 4; q++) {
            int u = tid + q * 512;          // 0..2047
            int row = u >> 6;               // 0..31
            int c4  = u & 63;
            uint4 vh = __ldcg((const uint4*)(hbh + (size_t)(b0 + row) * HH) + c4);
            uint4 vl = __ldcg((const uint4*)(hbl + (size_t)(b0 + row) * HH) + c4);
            *(uint4*)(h_hi + row * ROWW + c4 * 4) = vh;
            *(uint4*)(h_lo + row * ROWW + c4 * 4) = vl;
        }
        float4 xw4 = *(const float4*)&g_xw[((size_t)t * BB + b0 + pr) * GG + n0 + pj * 4];
        __syncthreads();

        float c[2][4] = {};
        const int arow0 = (mbase + r) * ROWW;
        const int arow1 = (mbase + r + 8) * ROWW;
        #pragma unroll 4
        for (int ks = 0; ks < 16; ks++) {
            int kw = kseg * 128 + ks * 8 + tq;
            uint32_t ah0 = h_hi[arow0 + kw];
            uint32_t ah1 = h_hi[arow1 + kw];
            uint32_t ah2 = h_hi[arow0 + kw + 4];
            uint32_t ah3 = h_hi[arow1 + kw + 4];
            uint32_t al0 = h_lo[arow0 + kw];
            uint32_t al1 = h_lo[arow1 + kw];
            uint32_t al2 = h_lo[arow0 + kw + 4];
            uint32_t al3 = h_lo[arow1 + kw + 4];
            #pragma unroll
            for (int j = 0; j < 2; j++) {
                int nr = (nbase + j * 8 + r) * ROWW + kw;
                uint32_t bh0 = u_hi[nr], bh1 = u_hi[nr + 4];
                uint32_t bl0 = u_lo[nr], bl1 = u_lo[nr + 4];
                mma_bf16(c[j], ah0, ah1, ah2, ah3, bh0, bh1);
                mma_bf16(c[j], ah0, ah1, ah2, ah3, bl0, bl1);
                mma_bf16(c[j], al0, al1, al2, al3, bh0, bh1);
            }
        }

        #pragma unroll
        for (int j = 0; j < 2; j++) {
            float* p = part + kseg * (32 * 68) + (mbase + r) * 68 + nbase + j * 8 + 2 * tq;
            *(float2*)p            = make_float2(c[j][0], c[j][1]);
            *(float2*)(p + 8 * 68) = make_float2(c[j][2], c[j][3]);
        }
        __syncthreads();

        {
            float4 p0 = *(const float4*)&part[pr * 68 + pj * 4];
            float4 p1 = *(const float4*)&part[32 * 68 + pr * 68 + pj * 4];
            float gi = p0.x + p1.x + xw4.x;
            float gf = p0.y + p1.y + xw4.y;
            float gc = p0.z + p1.z + xw4.z;
            float go = p0.w + p1.w + xw4.w;
            float it_ = 1.f / (1.f + __expf(-gi));
            float ft  = 1.f / (1.f + __expf(-gf));
            float ch  = tanhf(gc);
            float ot  = 1.f / (1.f + __expf(-go));
            float cn  = mr * (ft * cr + it_ * ch);
            cr = cn;
            float hn = ot * tanhf(cn);
            out[(size_t)t * BH + pidx] = hn;
            size_t nb = (size_t)((t + 1) & 1) * (BB * HH);
            __nv_bfloat16 hb = __float2bfloat16(hn);
            g_hBhi[nb + pidx] = hb;
            g_hBlo[nb + pidx] = __float2bfloat16(hn - __bfloat162float(hb));
        }

        // ---- per-rowgroup barrier: release add + acquire poll ----
        __syncthreads();
        if (tid == 0) {
            asm volatile("red.release.gpu.global.add.u32 [%0], %1;"
                         :: "l"(&g_ctr4[rg]), "r"(1u) : "memory");
            unsigned target = (unsigned)(t + 1) * 32u;
            unsigned cur;
            do {
                asm volatile("ld.acquire.gpu.global.u32 %0, [%1];"
                             : "=r"(cur) : "l"(&g_ctr4[rg]) : "memory");
            } while (cur < target);
        }
        __syncthreads();
    }

    g_c[pidx] = cr;
}

// copy h_T (== outputs[S-1]) and c_T into the output tail
__global__ void finalize(float* __restrict__ out)
{
    int i = blockIdx.x * blockDim.x + threadIdx.x;
    if (i < BH) {
        out[(size_t)SS * BH + i]      = out[(size_t)(SS - 1) * BH + i];
        out[(size_t)SS * BH + BH + i] = g_c[i];
    }
}

// ---------------------------------------------------------------------------
extern "C" void kernel_launch(void* const* d_in, const int* in_sizes, int n_in,
                              void* d_out, int out_size)
{
    const float* x     = (const float*)d_in[0];
    const float* h0    = (const float*)d_in[1];
    const float* c0    = (const float*)d_in[2];
    const float* alpha = (const float*)d_in[3];
    const float* beta  = (const float*)d_in[4];
    const float* theta = (const float*)d_in[5];
    const float* tspan = (const float*)d_in[6];
    const float* A     = (const float*)d_in[7];
    const float* Bm    = (const float*)d_in[8];
    const float* C     = (const float*)d_in[9];
    const float* Wi = (const float*)d_in[10];
    const float* Ui = (const float*)d_in[11];
    const float* bi = (const float*)d_in[12];
    const float* Wf = (const float*)d_in[13];
    const float* Uf = (const float*)d_in[14];
    const float* bf = (const float*)d_in[15];
    const float* Wc = (const float*)d_in[16];
    const float* Uc = (const float*)d_in[17];
    const float* bc = (const float*)d_in[18];
    const float* Wo = (const float*)d_in[19];
    const float* Uo = (const float*)d_in[20];
    const float* bo = (const float*)d_in[21];
    float* out = (float*)d_out;

    const int SMEM  = (2 * 64 * ROWW + 2 * 32 * ROWW + 2 * 32 * 68) * 4;  // 217088 B
    const int XSMEM = 2 * STGW * 4;                                        // 147456 B
    cudaFuncSetAttribute(lstm_persist, cudaFuncAttributeMaxDynamicSharedMemorySize, SMEM);
    cudaFuncSetAttribute(xw_mma, cudaFuncAttributeMaxDynamicSharedMemorySize, XSMEM);

    prep_U<<<dim3(16, 16, 4), dim3(32, 8)>>>(Ui, Uf, Uc, Uo);
    prep_W<<<dim3(16, 8, 4), dim3(32, 8)>>>(Wi, Wf, Wc, Wo);
    prep_state<<<(BB * HH + 255) / 256, 256>>>(h0, bi, bf, bc, bo);
    mdhp_kernel<<<BB, 512>>>(alpha, beta, theta, tspan, A, Bm, C);
    xsplit<<<(SS * BB * DD / 4) / 256, 256>>>(x);
    xw_mma<<<dim3(GG / 128, (SS * BB) / 128), 256, XSMEM>>>();
    lstm_persist<<<dim3(32, 4), 512, SMEM>>>(c0, out);
    finalize<<<(BH + 255) / 256, 256>>>(out);
}

// round 15
// speedup vs baseline: 1.2401x; 1.0108x over previous
#include <cuda_runtime.h>
#include <cuda_bf16.h>
#include <math.h>
#include <stdint.h>

// Problem dimensions (fixed by the dataset)
#define SS 512   // timesteps
#define BB 128   // batch
#define DD 256   // input dim
#define HH 512   // hidden
#define GG 2048  // 4*H (gate-interleaved: col n = j*4 + gate)
#define BH (BB*HH)

// Device scratch (no runtime allocation allowed)
__device__ float g_bias[GG];                 // interleaved bias [2048]
__device__ __nv_bfloat16 g_UThi[GG*HH];      // U'^T hi  [2048 n][512 k] bf16
__device__ __nv_bfloat16 g_UTlo[GG*HH];      // U'^T lo
__device__ __nv_bfloat16 g_WThi[GG*DD];      // W'^T hi  [2048 n][256 k] bf16
__device__ __nv_bfloat16 g_WTlo[GG*DD];      // W'^T lo
__device__ __nv_bfloat16 g_xhi[(size_t)SS*BB*DD];  // x hi  [65536 m][256 k] bf16
__device__ __nv_bfloat16 g_xlo[(size_t)SS*BB*DD];  // x lo
__device__ __nv_bfloat16 g_hBhi[2*BB*HH];    // double-buffered h hi [2][128 b][512 k]
__device__ __nv_bfloat16 g_hBlo[2*BB*HH];    // double-buffered h lo
__device__ float g_mdhp[BH];                 // tanh(alpha@A - (beta*ts)@B + theta@C)
__device__ float g_c[BH];                    // final cell state (for finalize)
__device__ float g_xw[(size_t)SS*BB*GG];     // precomputed x@W' + b  (512 MB)
__device__ unsigned g_ctr4[4];               // per-rowgroup barrier counters

// ---------------------------------------------------------------------------
// helpers
// ---------------------------------------------------------------------------
__device__ __forceinline__ void mma_bf16(float* c, uint32_t a0, uint32_t a1,
                                         uint32_t a2, uint32_t a3,
                                         uint32_t b0, uint32_t b1) {
    asm volatile("mma.sync.aligned.m16n8k16.row.col.f32.bf16.bf16.f32 "
        "{%0,%1,%2,%3}, {%4,%5,%6,%7}, {%8,%9}, {%0,%1,%2,%3};"
        : "+f"(c[0]), "+f"(c[1]), "+f"(c[2]), "+f"(c[3])
        : "r"(a0), "r"(a1), "r"(a2), "r"(a3), "r"(b0), "r"(b1));
}
__device__ __forceinline__ void ldsm_x4(uint32_t* r, uint32_t addr) {
    asm volatile("ldmatrix.sync.aligned.m8n8.x4.shared.b16 {%0,%1,%2,%3}, [%4];"
        : "=r"(r[0]), "=r"(r[1]), "=r"(r[2]), "=r"(r[3]) : "r"(addr));
}
__device__ __forceinline__ void ldsm_x2(uint32_t& r0, uint32_t& r1, uint32_t addr) {
    asm volatile("ldmatrix.sync.aligned.m8n8.x2.shared.b16 {%0,%1}, [%2];"
        : "=r"(r0), "=r"(r1) : "r"(addr));
}
__device__ __forceinline__ uint32_t smem_cast(const void* p) {
    return (uint32_t)__cvta_generic_to_shared(p);
}
__device__ __forceinline__ void cp16(uint32_t saddr, const void* g) {
    asm volatile("cp.async.ca.shared.global [%0], [%1], 16;" :: "r"(saddr), "l"(g));
}
__device__ __forceinline__ void cp16cg(uint32_t saddr, const void* g) {
    asm volatile("cp.async.cg.shared.global [%0], [%1], 16;" :: "r"(saddr), "l"(g));
}
#define CP_COMMIT() asm volatile("cp.async.commit_group;" ::: "memory")
#define CP_WAIT(n)  asm volatile("cp.async.wait_group %0;" :: "n"(n) : "memory")
#define BAR_SYNC(id, cnt) asm volatile("bar.sync %0, %1;" :: "r"(id), "r"(cnt) : "memory")

// ---------------------------------------------------------------------------
// prep_U: tile-transpose U_g[512 k][512 j] -> g_UT{hi,lo}[n=4j+g][k], coalesced.
// grid (16 jt, 16 kt, 4 g), block (32, 8)
// ---------------------------------------------------------------------------
__global__ void prep_U(const float* __restrict__ Ui, const float* __restrict__ Uf,
                       const float* __restrict__ Uc, const float* __restrict__ Uo)
{
    __shared__ float tile[32][33];
    const int g = blockIdx.z;
    const float* U = (g == 0) ? Ui : (g == 1) ? Uf : (g == 2) ? Uc : Uo;
    const int j0 = blockIdx.x * 32, k0 = blockIdx.y * 32;
    const int tx = threadIdx.x, ty = threadIdx.y;
    #pragma unroll
    for (int q = 0; q < 4; q++) {
        int kk = ty + q * 8;
        tile[kk][tx] = U[(size_t)(k0 + kk) * HH + j0 + tx];
    }
    __syncthreads();
    #pragma unroll
    for (int q = 0; q < 4; q++) {
        int jj = ty + q * 8;
        float u = tile[tx][jj];                 // = U[k0+tx][j0+jj]
        __nv_bfloat16 hi = __float2bfloat16(u);
        size_t o = (size_t)(4 * (j0 + jj) + g) * HH + k0 + tx;
        g_UThi[o] = hi;
        g_UTlo[o] = __float2bfloat16(u - __bfloat162float(hi));
    }
}

// prep_W: same for W_g[256 k][512 j] -> g_WT{hi,lo}[n][k]. grid (16 jt, 8 kt, 4 g)
__global__ void prep_W(const float* __restrict__ Wi, const float* __restrict__ Wf,
                       const float* __restrict__ Wc, const float* __restrict__ Wo)
{
    __shared__ float tile[32][33];
    const int g = blockIdx.z;
    const float* W = (g == 0) ? Wi : (g == 1) ? Wf : (g == 2) ? Wc : Wo;
    const int j0 = blockIdx.x * 32, k0 = blockIdx.y * 32;
    const int tx = threadIdx.x, ty = threadIdx.y;
    #pragma unroll
    for (int q = 0; q < 4; q++) {
        int kk = ty + q * 8;
        tile[kk][tx] = W[(size_t)(k0 + kk) * HH + j0 + tx];
    }
    __syncthreads();
    #pragma unroll
    for (int q = 0; q < 4; q++) {
        int jj = ty + q * 8;
        float w = tile[tx][jj];
        __nv_bfloat16 hi = __float2bfloat16(w);
        size_t o = (size_t)(4 * (j0 + jj) + g) * DD + k0 + tx;
        g_WThi[o] = hi;
        g_WTlo[o] = __float2bfloat16(w - __bfloat162float(hi));
    }
}

// split x into bf16 hi/lo (16.7M elements, 4 per thread)
__global__ void xsplit(const float* __restrict__ x)
{
    size_t i = (size_t)blockIdx.x * blockDim.x + threadIdx.x;   // float4 index
    float4 v = *((const float4*)x + i);
    __nv_bfloat16 h0 = __float2bfloat16(v.x);
    __nv_bfloat16 h1 = __float2bfloat16(v.y);
    __nv_bfloat16 h2 = __float2bfloat16(v.z);
    __nv_bfloat16 h3 = __float2bfloat16(v.w);
    __nv_bfloat16 l0 = __float2bfloat16(v.x - __bfloat162float(h0));
    __nv_bfloat16 l1 = __float2bfloat16(v.y - __bfloat162float(h1));
    __nv_bfloat16 l2 = __float2bfloat16(v.z - __bfloat162float(h2));
    __nv_bfloat16 l3 = __float2bfloat16(v.w - __bfloat162float(h3));
    ushort4 ph = make_ushort4(__bfloat16_as_ushort(h0), __bfloat16_as_ushort(h1),
                              __bfloat16_as_ushort(h2), __bfloat16_as_ushort(h3));
    ushort4 pl = make_ushort4(__bfloat16_as_ushort(l0), __bfloat16_as_ushort(l1),
                              __bfloat16_as_ushort(l2), __bfloat16_as_ushort(l3));
    *((ushort4*)g_xhi + i) = ph;
    *((ushort4*)g_xlo + i) = pl;
}

// ---------------------------------------------------------------------------
// mdhp = tanh(alpha @ A - (beta*tspan) @ B + theta @ C)   [B,H]
// ---------------------------------------------------------------------------
__global__ void mdhp_kernel(const float* __restrict__ alpha, const float* __restrict__ beta,
                            const float* __restrict__ theta, const float* __restrict__ tspan,
                            const float* __restrict__ A, const float* __restrict__ Bm,
                            const float* __restrict__ C)
{
    int b = blockIdx.x;
    int j = threadIdx.x;   // 0..511
    __shared__ float sa[256], sb[256], st[16];
    float ts = tspan[b];
    if (j < 256) {
        sa[j] = alpha[b * 256 + j];
        sb[j] = beta[b * 256 + j] * ts;
    }
    if (j < 16) st[j] = theta[b * 16 + j];
    __syncthreads();
    float acc = 0.f;
    #pragma unroll 8
    for (int k = 0; k < 256; k++)
        acc += sa[k] * A[k * 512 + j] - sb[k] * Bm[k * 512 + j];
    #pragma unroll
    for (int k = 0; k < 16; k++)
        acc += st[k] * C[k * 512 + j];
    g_mdhp[b * 512 + j] = tanhf(acc);
}

// zero barrier counters + bf16-split h0 + interleaved bias
__global__ void prep_state(const float* __restrict__ h0,
                           const float* __restrict__ bi, const float* __restrict__ bf,
                           const float* __restrict__ bc, const float* __restrict__ bo)
{
    int i = blockIdx.x * blockDim.x + threadIdx.x;
    if (i < 4) g_ctr4[i] = 0u;
    if (i < GG) {
        int j = i >> 2, g = i & 3;
        const float* bptr = (g == 0) ? bi : (g == 1) ? bf : (g == 2) ? bc : bo;
        g_bias[i] = bptr[j];
    }
    if (i < BB * HH) {
        float v = h0[i];                       // i = b*512 + k
        __nv_bfloat16 hi = __float2bfloat16(v);
        g_hBhi[i] = hi;
        g_hBlo[i] = __float2bfloat16(v - __bfloat162float(hi));
    }
}

// ---------------------------------------------------------------------------
// xW GEMM on mma.sync bf16 (2-way split, 3-term product), ldmatrix loads,
// cp.async double-buffered stages. (unchanged from round 14)
// ---------------------------------------------------------------------------
#define ROWX 36                 // uint32 words per padded row (32 data words)
#define STGW (4 * 128 * ROWX)   // words per stage (a_hi,a_lo,b_hi,b_lo)
__global__ __launch_bounds__(256, 1) void xw_mma()
{
    extern __shared__ __align__(16) uint32_t xs[];

    const int tid  = threadIdx.x;
    const int lane = tid & 31;
    const int wid  = tid >> 5;
    const int mbase = (wid & 3) * 32;       // 0,32,64,96
    const int nbase = (wid >> 2) * 64;      // 0,64
    const int r  = lane >> 2;               // 0..7
    const int tq = lane & 3;                // 0..3
    const int n0 = blockIdx.x * 128;
    const int m0 = blockIdx.y * 128;

    const uint32_t smBase = smem_cast(xs);
    const uint32_t STGB = STGW * 4;                 // stage bytes
    const uint32_t ARRB = 128 * ROWX * 4;           // array bytes

    const uint32_t aRowOff = ((mbase + (lane & 15)) * ROWX + (lane >> 4) * 4) << 2;
    const uint32_t aHiB = smBase + aRowOff;
    const uint32_t aLoB = smBase + ARRB + aRowOff;
    const uint32_t bRowOff = ((nbase + (lane & 7)) * ROWX + ((lane >> 3) & 1) * 4) << 2;
    const uint32_t bHiB = smBase + 2 * ARRB + bRowOff;
    const uint32_t bLoB = smBase + 3 * ARRB + bRowOff;
    const uint32_t FSTRIDE = (16 * ROWX) << 2;   // f: +16 rows
    const uint32_t JSTRIDE = (8 * ROWX) << 2;    // j: +8 rows

    float c[2][8][4];
    #pragma unroll
    for (int f = 0; f < 2; f++)
        #pragma unroll
        for (int j = 0; j < 8; j++)
            #pragma unroll
            for (int q = 0; q < 4; q++) c[f][j][q] = 0.f;

    auto load_stage = [&](int s, int kc) {
        const int k0 = kc * 64;
        const uint32_t sb = smBase + s * STGB;
        #pragma unroll
        for (int q = 0; q < 4; q++) {
            int u = tid + q * 256;          // 0..1023
            int row = u >> 3;               // 0..127
            int c4  = u & 7;
            uint32_t so = (row * ROWX + c4 * 4) << 2;
            cp16(sb + so,            (const void*)((const uint4*)(g_xhi  + (size_t)(m0 + row) * DD + k0) + c4));
            cp16(sb + ARRB + so,     (const void*)((const uint4*)(g_xlo  + (size_t)(m0 + row) * DD + k0) + c4));
            cp16(sb + 2 * ARRB + so, (const void*)((const uint4*)(g_WThi + (size_t)(n0 + row) * DD + k0) + c4));
            cp16(sb + 3 * ARRB + so, (const void*)((const uint4*)(g_WTlo + (size_t)(n0 + row) * DD + k0) + c4));
        }
    };

    load_stage(0, 0);
    CP_COMMIT();

    for (int kc = 0; kc < 4; kc++) {
        if (kc < 3) {
            load_stage((kc + 1) & 1, kc + 1);
            CP_COMMIT();
            CP_WAIT(1);
        } else {
            CP_WAIT(0);
        }
        __syncthreads();

        const uint32_t so = (kc & 1) * STGB;
        #pragma unroll
        for (int ks = 0; ks < 4; ks++) {
            const uint32_t ksOff = so + ks * 32;
            uint32_t ah[2][4], al[2][4];
            ldsm_x4(ah[0], aHiB + ksOff);
            ldsm_x4(ah[1], aHiB + FSTRIDE + ksOff);
            ldsm_x4(al[0], aLoB + ksOff);
            ldsm_x4(al[1], aLoB + FSTRIDE + ksOff);
            #pragma unroll
            for (int j = 0; j < 8; j++) {
                uint32_t bh0, bh1, bl0, bl1;
                ldsm_x2(bh0, bh1, bHiB + j * JSTRIDE + ksOff);
                ldsm_x2(bl0, bl1, bLoB + j * JSTRIDE + ksOff);
                #pragma unroll
                for (int f = 0; f < 2; f++) {
                    mma_bf16(c[f][j], ah[f][0], ah[f][1], ah[f][2], ah[f][3], bh0, bh1);
                    mma_bf16(c[f][j], ah[f][0], ah[f][1], ah[f][2], ah[f][3], bl0, bl1);
                    mma_bf16(c[f][j], al[f][0], al[f][1], al[f][2], al[f][3], bh0, bh1);
                }
            }
        }
        __syncthreads();
    }

    #pragma unroll
    for (int f = 0; f < 2; f++) {
        int row0 = m0 + mbase + f * 16 + r;
        #pragma unroll
        for (int j = 0; j < 8; j++) {
            int col = n0 + nbase + j * 8 + 2 * tq;
            float2 bb = *(const float2*)&g_bias[col];
            float2 o0 = make_float2(c[f][j][0] + bb.x, c[f][j][1] + bb.y);
            float2 o1 = make_float2(c[f][j][2] + bb.x, c[f][j][3] + bb.y);
            __stcs((float2*)&g_xw[(size_t)row0 * GG + col], o0);
            __stcs((float2*)&g_xw[(size_t)(row0 + 8) * GG + col], o1);
        }
    }
}

// ---------------------------------------------------------------------------
// Persistent LSTM recurrence on mma.sync bf16 — r8 GEMM/gates (proven),
// h staging via cp.async.cg with per-kseg-group named barriers (each K-half
// group stages only its own half and proceeds independently to the mma).
// ---------------------------------------------------------------------------
#define ROWW 260   // uint32 words per padded bf16 row (520 bf16; 256 data words)
__global__ __launch_bounds__(512) void lstm_persist(const float* __restrict__ c0,
                                                    float* __restrict__ out)
{
    extern __shared__ __align__(16) uint32_t smw[];
    uint32_t* u_hi = smw;                               // [64][260]
    uint32_t* u_lo = smw + 64 * ROWW;                   // [64][260]
    uint32_t* h_hi = smw + 2 * 64 * ROWW;               // [32][260]
    uint32_t* h_lo = smw + 2 * 64 * ROWW + 32 * ROWW;   // [32][260]
    float*    part = (float*)(smw + 2 * 64 * ROWW + 2 * 32 * ROWW); // [2][32][68]

    const int tid = threadIdx.x;
    const int bx  = blockIdx.x;            // 0..31 col block
    const int rg  = blockIdx.y;            // 0..3  row group
    const int n0  = bx * 64;               // interleaved gate-col base
    const int b0  = rg * 32;               // batch row base

    const int lane = tid & 31;
    const int wid  = tid >> 5;             // 0..15
    const int kseg  = wid >> 3;            // 0..1  K half (also staging group)
    const int ow    = wid & 7;             // 0..7  output warp
    const int mbase = (ow >> 2) * 16;      // 0 or 16
    const int nbase = (ow & 3) * 16;       // 0,16,32,48
    const int r  = lane >> 2;              // 0..7
    const int tq = lane & 3;               // 0..3

    const int pr = tid >> 4;               // 0..31
    const int pj = tid & 15;               // 0..15
    const int jglob = bx * 16 + pj;
    const int pidx = (b0 + pr) * HH + jglob;

    // staging mapping: group kseg loads its K-half (c4 in [kseg*32, kseg*32+32))
    const int gt = tid & 255;              // thread id within group

    // ---- load persistent U'^T slice (bf16 hi/lo) ----
    #pragma unroll
    for (int q = 0; q < 8; q++) {
        int u = tid + q * 512;              // 0..4095
        int row = u >> 6;                   // 0..63
        int c4  = u & 63;
        uint4 vh = *((const uint4*)(g_UThi + (size_t)(n0 + row) * HH) + c4);
        uint4 vl = *((const uint4*)(g_UTlo + (size_t)(n0 + row) * HH) + c4);
        *(uint4*)(u_hi + row * ROWW + c4 * 4) = vh;
        *(uint4*)(u_lo + row * ROWW + c4 * 4) = vl;
    }

    float cr = c0[pidx];
    float mr = g_mdhp[pidx];
    __syncthreads();

    for (int t = 0; t < SS; t++) {
        // ---- stage own K-half of h via cp.async.cg (L2-coherent) ----
        const __nv_bfloat16* hbh = g_hBhi + (size_t)(t & 1) * (BB * HH);
        const __nv_bfloat16* hbl = g_hBlo + (size_t)(t & 1) * (BB * HH);
        #pragma unroll
        for (int q = 0; q < 4; q++) {
            int u = gt + q * 256;           // 0..1023
            int row = u >> 5;               // 0..31
            int c4  = kseg * 32 + (u & 31); // this group's K-half
            uint32_t so = (row * ROWW + c4 * 4) << 2;
            cp16cg(smem_cast(h_hi) + so, (const void*)((const uint4*)(hbh + (size_t)(b0 + row) * HH) + c4));
            cp16cg(smem_cast(h_lo) + so, (const void*)((const uint4*)(hbl + (size_t)(b0 + row) * HH) + c4));
        }
        CP_COMMIT();
        float4 xw4 = *(const float4*)&g_xw[((size_t)t * BB + b0 + pr) * GG + n0 + pj * 4];
        CP_WAIT(0);
        BAR_SYNC(1 + kseg, 256);            // group-local: own K-half staged

        // ---- GEMM: warp tile m16 x n16, this group's K half ----
        float c[2][4] = {};
        const int arow0 = (mbase + r) * ROWW;
        const int arow1 = (mbase + r + 8) * ROWW;
        #pragma unroll 4
        for (int ks = 0; ks < 16; ks++) {
            int kw = kseg * 128 + ks * 8 + tq;
            uint32_t ah0 = h_hi[arow0 + kw];
            uint32_t ah1 = h_hi[arow1 + kw];
            uint32_t ah2 = h_hi[arow0 + kw + 4];
            uint32_t ah3 = h_hi[arow1 + kw + 4];
            uint32_t al0 = h_lo[arow0 + kw];
            uint32_t al1 = h_lo[arow1 + kw];
            uint32_t al2 = h_lo[arow0 + kw + 4];
            uint32_t al3 = h_lo[arow1 + kw + 4];
            #pragma unroll
            for (int j = 0; j < 2; j++) {
                int nr = (nbase + j * 8 + r) * ROWW + kw;
                uint32_t bh0 = u_hi[nr], bh1 = u_hi[nr + 4];
                uint32_t bl0 = u_lo[nr], bl1 = u_lo[nr + 4];
                mma_bf16(c[j], ah0, ah1, ah2, ah3, bh0, bh1);
                mma_bf16(c[j], ah0, ah1, ah2, ah3, bl0, bl1);
                mma_bf16(c[j], al0, al1, al2, al3, bh0, bh1);
            }
        }

        #pragma unroll
        for (int j = 0; j < 2; j++) {
            float* p = part + kseg * (32 * 68) + (mbase + r) * 68 + nbase + j * 8 + 2 * tq;
            *(float2*)p            = make_float2(c[j][0], c[j][1]);
            *(float2*)(p + 8 * 68) = make_float2(c[j][2], c[j][3]);
        }
        __syncthreads();

        {
            float4 p0 = *(const float4*)&part[pr * 68 + pj * 4];
            float4 p1 = *(const float4*)&part[32 * 68 + pr * 68 + pj * 4];
            float gi = p0.x + p1.x + xw4.x;
            float gf = p0.y + p1.y + xw4.y;
            float gc = p0.z + p1.z + xw4.z;
            float go = p0.w + p1.w + xw4.w;
            float it_ = 1.f / (1.f + __expf(-gi));
            float ft  = 1.f / (1.f + __expf(-gf));
            float ch  = tanhf(gc);
            float ot  = 1.f / (1.f + __expf(-go));
            float cn  = mr * (ft * cr + it_ * ch);
            cr = cn;
            float hn = ot * tanhf(cn);
            out[(size_t)t * BH + pidx] = hn;
            size_t nb = (size_t)((t + 1) & 1) * (BB * HH);
            __nv_bfloat16 hb = __float2bfloat16(hn);
            g_hBhi[nb + pidx] = hb;
            g_hBlo[nb + pidx] = __float2bfloat16(hn - __bfloat162float(hb));
        }

        // ---- per-rowgroup barrier: release add + acquire poll ----
        __syncthreads();
        if (tid == 0) {
            asm volatile("red.release.gpu.global.add.u32 [%0], %1;"
                         :: "l"(&g_ctr4[rg]), "r"(1u) : "memory");
            unsigned target = (unsigned)(t + 1) * 32u;
            unsigned cur;
            do {
                asm volatile("ld.acquire.gpu.global.u32 %0, [%1];"
                             : "=r"(cur) : "l"(&g_ctr4[rg]) : "memory");
            } while (cur < target);
        }
        __syncthreads();
    }

    g_c[pidx] = cr;
}

// copy h_T (== outputs[S-1]) and c_T into the output tail
__global__ void finalize(float* __restrict__ out)
{
    int i = blockIdx.x * blockDim.x + threadIdx.x;
    if (i < BH) {
        out[(size_t)SS * BH + i]      = out[(size_t)(SS - 1) * BH + i];
        out[(size_t)SS * BH + BH + i] = g_c[i];
    }
}

// ---------------------------------------------------------------------------
extern "C" void kernel_launch(void* const* d_in, const int* in_sizes, int n_in,
                              void* d_out, int out_size)
{
    const float* x     = (const float*)d_in[0];
    const float* h0    = (const float*)d_in[1];
    const float* c0    = (const float*)d_in[2];
    const float* alpha = (const float*)d_in[3];
    const float* beta  = (const float*)d_in[4];
    const float* theta = (const float*)d_in[5];
    const float* tspan = (const float*)d_in[6];
    const float* A     = (const float*)d_in[7];
    const float* Bm    = (const float*)d_in[8];
    const float* C     = (const float*)d_in[9];
    const float* Wi = (const float*)d_in[10];
    const float* Ui = (const float*)d_in[11];
    const float* bi = (const float*)d_in[12];
    const float* Wf = (const float*)d_in[13];
    const float* Uf = (const float*)d_in[14];
    const float* bf = (const float*)d_in[15];
    const float* Wc = (const float*)d_in[16];
    const float* Uc = (const float*)d_in[17];
    const float* bc = (const float*)d_in[18];
    const float* Wo = (const float*)d_in[19];
    const float* Uo = (const float*)d_in[20];
    const float* bo = (const float*)d_in[21];
    float* out = (float*)d_out;

    const int SMEM  = (2 * 64 * ROWW + 2 * 32 * ROWW + 2 * 32 * 68) * 4;  // 217088 B
    const int XSMEM = 2 * STGW * 4;                                        // 147456 B
    cudaFuncSetAttribute(lstm_persist, cudaFuncAttributeMaxDynamicSharedMemorySize, SMEM);
    cudaFuncSetAttribute(xw_mma, cudaFuncAttributeMaxDynamicSharedMemorySize, XSMEM);

    prep_U<<<dim3(16, 16, 4), dim3(32, 8)>>>(Ui, Uf, Uc, Uo);
    prep_W<<<dim3(16, 8, 4), dim3(32, 8)>>>(Wi, Wf, Wc, Wo);
    prep_state<<<(BB * HH + 255) / 256, 256>>>(h0, bi, bf, bc, bo);
    mdhp_kernel<<<BB, 512>>>(alpha, beta, theta, tspan, A, Bm, C);
    xsplit<<<(SS * BB * DD / 4) / 256, 256>>>(x);
    xw_mma<<<dim3(GG / 128, (SS * BB) / 128), 256, XSMEM>>>();
    lstm_persist<<<dim3(32, 4), 512, SMEM>>>(c0, out);
    finalize<<<(BH + 255) / 256, 256>>>(out);
}

// round 16
// speedup vs baseline: 1.2830x; 1.0346x over previous
#include <cuda_runtime.h>
#include <cuda_bf16.h>
#include <math.h>
#include <stdint.h>

// Problem dimensions (fixed by the dataset)
#define SS 512   // timesteps
#define BB 128   // batch
#define DD 256   // input dim
#define HH 512   // hidden
#define GG 2048  // 4*H (gate-interleaved: col n = j*4 + gate)
#define BH (BB*HH)

// Device scratch (no runtime allocation allowed)
__device__ float g_bias[GG];                 // interleaved bias [2048]
__device__ __nv_bfloat16 g_UThi[GG*HH];      // U'^T hi  [2048 n][512 k] bf16
__device__ __nv_bfloat16 g_UTlo[GG*HH];      // U'^T lo
__device__ __nv_bfloat16 g_WThi[GG*DD];      // W'^T hi  [2048 n][256 k] bf16
__device__ __nv_bfloat16 g_WTlo[GG*DD];      // W'^T lo
__device__ __nv_bfloat16 g_xhi[(size_t)SS*BB*DD];  // x hi  [65536 m][256 k] bf16
__device__ __nv_bfloat16 g_xlo[(size_t)SS*BB*DD];  // x lo
__device__ __nv_bfloat16 g_hBhi[2*BB*HH];    // double-buffered h hi [2][128 b][512 k]
__device__ __nv_bfloat16 g_hBlo[2*BB*HH];    // double-buffered h lo
__device__ float g_mdhp[BH];                 // tanh(alpha@A - (beta*ts)@B + theta@C)
__device__ float g_c[BH];                    // final cell state (for finalize)
__device__ float g_xw[(size_t)SS*BB*GG];     // precomputed x@W' + b  (512 MB)
__device__ unsigned g_ctr8[8];               // per-(rowgroup, K-half) barrier counters

// ---------------------------------------------------------------------------
// helpers
// ---------------------------------------------------------------------------
__device__ __forceinline__ void mma_bf16(float* c, uint32_t a0, uint32_t a1,
                                         uint32_t a2, uint32_t a3,
                                         uint32_t b0, uint32_t b1) {
    asm volatile("mma.sync.aligned.m16n8k16.row.col.f32.bf16.bf16.f32 "
        "{%0,%1,%2,%3}, {%4,%5,%6,%7}, {%8,%9}, {%0,%1,%2,%3};"
        : "+f"(c[0]), "+f"(c[1]), "+f"(c[2]), "+f"(c[3])
        : "r"(a0), "r"(a1), "r"(a2), "r"(a3), "r"(b0), "r"(b1));
}
__device__ __forceinline__ void ldsm_x4(uint32_t* r, uint32_t addr) {
    asm volatile("ldmatrix.sync.aligned.m8n8.x4.shared.b16 {%0,%1,%2,%3}, [%4];"
        : "=r"(r[0]), "=r"(r[1]), "=r"(r[2]), "=r"(r[3]) : "r"(addr));
}
__device__ __forceinline__ void ldsm_x2(uint32_t& r0, uint32_t& r1, uint32_t addr) {
    asm volatile("ldmatrix.sync.aligned.m8n8.x2.shared.b16 {%0,%1}, [%2];"
        : "=r"(r0), "=r"(r1) : "r"(addr));
}
__device__ __forceinline__ uint32_t smem_cast(const void* p) {
    return (uint32_t)__cvta_generic_to_shared(p);
}
__device__ __forceinline__ void cp16(uint32_t saddr, const void* g) {
    asm volatile("cp.async.ca.shared.global [%0], [%1], 16;" :: "r"(saddr), "l"(g));
}
__device__ __forceinline__ void cp16cg(uint32_t saddr, const void* g) {
    asm volatile("cp.async.cg.shared.global [%0], [%1], 16;" :: "r"(saddr), "l"(g));
}
#define CP_COMMIT() asm volatile("cp.async.commit_group;" ::: "memory")
#define CP_WAIT(n)  asm volatile("cp.async.wait_group %0;" :: "n"(n) : "memory")
#define BAR_SYNC(id, cnt) asm volatile("bar.sync %0, %1;" :: "r"(id), "r"(cnt) : "memory")

// ---------------------------------------------------------------------------
// prep_U: tile-transpose U_g[512 k][512 j] -> g_UT{hi,lo}[n=4j+g][k], coalesced.
// grid (16 jt, 16 kt, 4 g), block (32, 8)
// ---------------------------------------------------------------------------
__global__ void prep_U(const float* __restrict__ Ui, const float* __restrict__ Uf,
                       const float* __restrict__ Uc, const float* __restrict__ Uo)
{
    __shared__ float tile[32][33];
    const int g = blockIdx.z;
    const float* U = (g == 0) ? Ui : (g == 1) ? Uf : (g == 2) ? Uc : Uo;
    const int j0 = blockIdx.x * 32, k0 = blockIdx.y * 32;
    const int tx = threadIdx.x, ty = threadIdx.y;
    #pragma unroll
    for (int q = 0; q < 4; q++) {
        int kk = ty + q * 8;
        tile[kk][tx] = U[(size_t)(k0 + kk) * HH + j0 + tx];
    }
    __syncthreads();
    #pragma unroll
    for (int q = 0; q < 4; q++) {
        int jj = ty + q * 8;
        float u = tile[tx][jj];                 // = U[k0+tx][j0+jj]
        __nv_bfloat16 hi = __float2bfloat16(u);
        size_t o = (size_t)(4 * (j0 + jj) + g) * HH + k0 + tx;
        g_UThi[o] = hi;
        g_UTlo[o] = __float2bfloat16(u - __bfloat162float(hi));
    }
}

// prep_W: same for W_g[256 k][512 j] -> g_WT{hi,lo}[n][k]. grid (16 jt, 8 kt, 4 g)
__global__ void prep_W(const float* __restrict__ Wi, const float* __restrict__ Wf,
                       const float* __restrict__ Wc, const float* __restrict__ Wo)
{
    __shared__ float tile[32][33];
    const int g = blockIdx.z;
    const float* W = (g == 0) ? Wi : (g == 1) ? Wf : (g == 2) ? Wc : Wo;
    const int j0 = blockIdx.x * 32, k0 = blockIdx.y * 32;
    const int tx = threadIdx.x, ty = threadIdx.y;
    #pragma unroll
    for (int q = 0; q < 4; q++) {
        int kk = ty + q * 8;
        tile[kk][tx] = W[(size_t)(k0 + kk) * HH + j0 + tx];
    }
    __syncthreads();
    #pragma unroll
    for (int q = 0; q < 4; q++) {
        int jj = ty + q * 8;
        float w = tile[tx][jj];
        __nv_bfloat16 hi = __float2bfloat16(w);
        size_t o = (size_t)(4 * (j0 + jj) + g) * DD + k0 + tx;
        g_WThi[o] = hi;
        g_WTlo[o] = __float2bfloat16(w - __bfloat162float(hi));
    }
}

// split x into bf16 hi/lo (16.7M elements, 4 per thread)
__global__ void xsplit(const float* __restrict__ x)
{
    size_t i = (size_t)blockIdx.x * blockDim.x + threadIdx.x;   // float4 index
    float4 v = *((const float4*)x + i);
    __nv_bfloat16 h0 = __float2bfloat16(v.x);
    __nv_bfloat16 h1 = __float2bfloat16(v.y);
    __nv_bfloat16 h2 = __float2bfloat16(v.z);
    __nv_bfloat16 h3 = __float2bfloat16(v.w);
    __nv_bfloat16 l0 = __float2bfloat16(v.x - __bfloat162float(h0));
    __nv_bfloat16 l1 = __float2bfloat16(v.y - __bfloat162float(h1));
    __nv_bfloat16 l2 = __float2bfloat16(v.z - __bfloat162float(h2));
    __nv_bfloat16 l3 = __float2bfloat16(v.w - __bfloat162float(h3));
    ushort4 ph = make_ushort4(__bfloat16_as_ushort(h0), __bfloat16_as_ushort(h1),
                              __bfloat16_as_ushort(h2), __bfloat16_as_ushort(h3));
    ushort4 pl = make_ushort4(__bfloat16_as_ushort(l0), __bfloat16_as_ushort(l1),
                              __bfloat16_as_ushort(l2), __bfloat16_as_ushort(l3));
    *((ushort4*)g_xhi + i) = ph;
    *((ushort4*)g_xlo + i) = pl;
}

// ---------------------------------------------------------------------------
// mdhp = tanh(alpha @ A - (beta*tspan) @ B + theta @ C)   [B,H]
// ---------------------------------------------------------------------------
__global__ void mdhp_kernel(const float* __restrict__ alpha, const float* __restrict__ beta,
                            const float* __restrict__ theta, const float* __restrict__ tspan,
                            const float* __restrict__ A, const float* __restrict__ Bm,
                            const float* __restrict__ C)
{
    int b = blockIdx.x;
    int j = threadIdx.x;   // 0..511
    __shared__ float sa[256], sb[256], st[16];
    float ts = tspan[b];
    if (j < 256) {
        sa[j] = alpha[b * 256 + j];
        sb[j] = beta[b * 256 + j] * ts;
    }
    if (j < 16) st[j] = theta[b * 16 + j];
    __syncthreads();
    float acc = 0.f;
    #pragma unroll 8
    for (int k = 0; k < 256; k++)
        acc += sa[k] * A[k * 512 + j] - sb[k] * Bm[k * 512 + j];
    #pragma unroll
    for (int k = 0; k < 16; k++)
        acc += st[k] * C[k * 512 + j];
    g_mdhp[b * 512 + j] = tanhf(acc);
}

// zero barrier counters + bf16-split h0 + interleaved bias
__global__ void prep_state(const float* __restrict__ h0,
                           const float* __restrict__ bi, const float* __restrict__ bf,
                           const float* __restrict__ bc, const float* __restrict__ bo)
{
    int i = blockIdx.x * blockDim.x + threadIdx.x;
    if (i < 8) g_ctr8[i] = 0u;
    if (i < GG) {
        int j = i >> 2, g = i & 3;
        const float* bptr = (g == 0) ? bi : (g == 1) ? bf : (g == 2) ? bc : bo;
        g_bias[i] = bptr[j];
    }
    if (i < BB * HH) {
        float v = h0[i];                       // i = b*512 + k
        __nv_bfloat16 hi = __float2bfloat16(v);
        g_hBhi[i] = hi;
        g_hBlo[i] = __float2bfloat16(v - __bfloat162float(hi));
    }
}

// ---------------------------------------------------------------------------
// xW GEMM on mma.sync bf16 (2-way split, 3-term product), ldmatrix loads,
// cp.async double-buffered stages. (unchanged from round 14/15)
// ---------------------------------------------------------------------------
#define ROWX 36                 // uint32 words per padded row (32 data words)
#define STGW (4 * 128 * ROWX)   // words per stage (a_hi,a_lo,b_hi,b_lo)
__global__ __launch_bounds__(256, 1) void xw_mma()
{
    extern __shared__ __align__(16) uint32_t xs[];

    const int tid  = threadIdx.x;
    const int lane = tid & 31;
    const int wid  = tid >> 5;
    const int mbase = (wid & 3) * 32;       // 0,32,64,96
    const int nbase = (wid >> 2) * 64;      // 0,64
    const int r  = lane >> 2;               // 0..7
    const int tq = lane & 3;                // 0..3
    const int n0 = blockIdx.x * 128;
    const int m0 = blockIdx.y * 128;

    const uint32_t smBase = smem_cast(xs);
    const uint32_t STGB = STGW * 4;                 // stage bytes
    const uint32_t ARRB = 128 * ROWX * 4;           // array bytes

    const uint32_t aRowOff = ((mbase + (lane & 15)) * ROWX + (lane >> 4) * 4) << 2;
    const uint32_t aHiB = smBase + aRowOff;
    const uint32_t aLoB = smBase + ARRB + aRowOff;
    const uint32_t bRowOff = ((nbase + (lane & 7)) * ROWX + ((lane >> 3) & 1) * 4) << 2;
    const uint32_t bHiB = smBase + 2 * ARRB + bRowOff;
    const uint32_t bLoB = smBase + 3 * ARRB + bRowOff;
    const uint32_t FSTRIDE = (16 * ROWX) << 2;   // f: +16 rows
    const uint32_t JSTRIDE = (8 * ROWX) << 2;    // j: +8 rows

    float c[2][8][4];
    #pragma unroll
    for (int f = 0; f < 2; f++)
        #pragma unroll
        for (int j = 0; j < 8; j++)
            #pragma unroll
            for (int q = 0; q < 4; q++) c[f][j][q] = 0.f;

    auto load_stage = [&](int s, int kc) {
        const int k0 = kc * 64;
        const uint32_t sb = smBase + s * STGB;
        #pragma unroll
        for (int q = 0; q < 4; q++) {
            int u = tid + q * 256;          // 0..1023
            int row = u >> 3;               // 0..127
            int c4  = u & 7;
            uint32_t so = (row * ROWX + c4 * 4) << 2;
            cp16(sb + so,            (const void*)((const uint4*)(g_xhi  + (size_t)(m0 + row) * DD + k0) + c4));
            cp16(sb + ARRB + so,     (const void*)((const uint4*)(g_xlo  + (size_t)(m0 + row) * DD + k0) + c4));
            cp16(sb + 2 * ARRB + so, (const void*)((const uint4*)(g_WThi + (size_t)(n0 + row) * DD + k0) + c4));
            cp16(sb + 3 * ARRB + so, (const void*)((const uint4*)(g_WTlo + (size_t)(n0 + row) * DD + k0) + c4));
        }
    };

    load_stage(0, 0);
    CP_COMMIT();

    for (int kc = 0; kc < 4; kc++) {
        if (kc < 3) {
            load_stage((kc + 1) & 1, kc + 1);
            CP_COMMIT();
            CP_WAIT(1);
        } else {
            CP_WAIT(0);
        }
        __syncthreads();

        const uint32_t so = (kc & 1) * STGB;
        #pragma unroll
        for (int ks = 0; ks < 4; ks++) {
            const uint32_t ksOff = so + ks * 32;
            uint32_t ah[2][4], al[2][4];
            ldsm_x4(ah[0], aHiB + ksOff);
            ldsm_x4(ah[1], aHiB + FSTRIDE + ksOff);
            ldsm_x4(al[0], aLoB + ksOff);
            ldsm_x4(al[1], aLoB + FSTRIDE + ksOff);
            #pragma unroll
            for (int j = 0; j < 8; j++) {
                uint32_t bh0, bh1, bl0, bl1;
                ldsm_x2(bh0, bh1, bHiB + j * JSTRIDE + ksOff);
                ldsm_x2(bl0, bl1, bLoB + j * JSTRIDE + ksOff);
                #pragma unroll
                for (int f = 0; f < 2; f++) {
                    mma_bf16(c[f][j], ah[f][0], ah[f][1], ah[f][2], ah[f][3], bh0, bh1);
                    mma_bf16(c[f][j], ah[f][0], ah[f][1], ah[f][2], ah[f][3], bl0, bl1);
                    mma_bf16(c[f][j], al[f][0], al[f][1], al[f][2], al[f][3], bh0, bh1);
                }
            }
        }
        __syncthreads();
    }

    #pragma unroll
    for (int f = 0; f < 2; f++) {
        int row0 = m0 + mbase + f * 16 + r;
        #pragma unroll
        for (int j = 0; j < 8; j++) {
            int col = n0 + nbase + j * 8 + 2 * tq;
            float2 bb = *(const float2*)&g_bias[col];
            float2 o0 = make_float2(c[f][j][0] + bb.x, c[f][j][1] + bb.y);
            float2 o1 = make_float2(c[f][j][2] + bb.x, c[f][j][3] + bb.y);
            __stcs((float2*)&g_xw[(size_t)row0 * GG + col], o0);
            __stcs((float2*)&g_xw[(size_t)(row0 + 8) * GG + col], o1);
        }
    }
}

// ---------------------------------------------------------------------------
// Persistent LSTM recurrence on mma.sync bf16 — r8 GEMM/gates (proven).
// NEW: split half-barriers. kseg group g only consumes h[k in half g], which
// is produced solely by col-blocks bx in that half (jglob = 16*bx + pj).
// Each block arrives once per step at ctr8[rg*2 + (bx>>4)]; each kseg group
// polls only ctr8[rg*2 + kseg] (16 producers) and proceeds independently
// through staging and mma. Joint syncs only at part-reduce and pre-arrive.
// ---------------------------------------------------------------------------
#define ROWW 260   // uint32 words per padded bf16 row (520 bf16; 256 data words)
__global__ __launch_bounds__(512) void lstm_persist(const float* __restrict__ c0,
                                                    float* __restrict__ out)
{
    extern __shared__ __align__(16) uint32_t smw[];
    uint32_t* u_hi = smw;                               // [64][260]
    uint32_t* u_lo = smw + 64 * ROWW;                   // [64][260]
    uint32_t* h_hi = smw + 2 * 64 * ROWW;               // [32][260]
    uint32_t* h_lo = smw + 2 * 64 * ROWW + 32 * ROWW;   // [32][260]
    float*    part = (float*)(smw + 2 * 64 * ROWW + 2 * 32 * ROWW); // [2][32][68]

    const int tid = threadIdx.x;
    const int bx  = blockIdx.x;            // 0..31 col block
    const int rg  = blockIdx.y;            // 0..3  row group
    const int n0  = bx * 64;               // interleaved gate-col base
    const int b0  = rg * 32;               // batch row base

    const int lane = tid & 31;
    const int wid  = tid >> 5;             // 0..15
    const int kseg  = wid >> 3;            // 0..1  K half (also staging group)
    const int ow    = wid & 7;             // 0..7  output warp
    const int mbase = (ow >> 2) * 16;      // 0 or 16
    const int nbase = (ow & 3) * 16;       // 0,16,32,48
    const int r  = lane >> 2;              // 0..7
    const int tq = lane & 3;               // 0..3

    const int pr = tid >> 4;               // 0..31
    const int pj = tid & 15;               // 0..15
    const int jglob = bx * 16 + pj;
    const int pidx = (b0 + pr) * HH + jglob;

    const int gt = tid & 255;              // thread id within kseg group
    unsigned* ctr_mine = &g_ctr8[rg * 2 + (bx >> 4)];   // this block arrives here
    unsigned* ctr_need = &g_ctr8[rg * 2 + kseg];        // this group waits here

    // ---- load persistent U'^T slice (bf16 hi/lo) ----
    #pragma unroll
    for (int q = 0; q < 8; q++) {
        int u = tid + q * 512;              // 0..4095
        int row = u >> 6;                   // 0..63
        int c4  = u & 63;
        uint4 vh = *((const uint4*)(g_UThi + (size_t)(n0 + row) * HH) + c4);
        uint4 vl = *((const uint4*)(g_UTlo + (size_t)(n0 + row) * HH) + c4);
        *(uint4*)(u_hi + row * ROWW + c4 * 4) = vh;
        *(uint4*)(u_lo + row * ROWW + c4 * 4) = vl;
    }

    float cr = c0[pidx];
    float mr = g_mdhp[pidx];
    __syncthreads();

    for (int t = 0; t < SS; t++) {
        // prefetch xw quad (DRAM latency overlaps the wait below)
        float4 xw4 = *(const float4*)&g_xw[((size_t)t * BB + b0 + pr) * GG + n0 + pj * 4];

        // ---- group-level wait: producers of our K-half finished step t-1 ----
        if (gt == 0) {
            unsigned target = (unsigned)t * 16u;
            unsigned cur;
            do {
                asm volatile("ld.acquire.gpu.global.u32 %0, [%1];"
                             : "=r"(cur) : "l"(ctr_need) : "memory");
            } while (cur < target);
        }
        BAR_SYNC(1 + kseg, 256);

        // ---- stage own K-half of h via cp.async.cg (L2-coherent) ----
        const __nv_bfloat16* hbh = g_hBhi + (size_t)(t & 1) * (BB * HH);
        const __nv_bfloat16* hbl = g_hBlo + (size_t)(t & 1) * (BB * HH);
        #pragma unroll
        for (int q = 0; q < 4; q++) {
            int u = gt + q * 256;           // 0..1023
            int row = u >> 5;               // 0..31
            int c4  = kseg * 32 + (u & 31); // this group's K-half
            uint32_t so = (row * ROWW + c4 * 4) << 2;
            cp16cg(smem_cast(h_hi) + so, (const void*)((const uint4*)(hbh + (size_t)(b0 + row) * HH) + c4));
            cp16cg(smem_cast(h_lo) + so, (const void*)((const uint4*)(hbl + (size_t)(b0 + row) * HH) + c4));
        }
        CP_COMMIT();
        CP_WAIT(0);
        BAR_SYNC(1 + kseg, 256);            // group-local: own K-half staged

        // ---- GEMM: warp tile m16 x n16, this group's K half ----
        float c[2][4] = {};
        const int arow0 = (mbase + r) * ROWW;
        const int arow1 = (mbase + r + 8) * ROWW;
        #pragma unroll 4
        for (int ks = 0; ks < 16; ks++) {
            int kw = kseg * 128 + ks * 8 + tq;
            uint32_t ah0 = h_hi[arow0 + kw];
            uint32_t ah1 = h_hi[arow1 + kw];
            uint32_t ah2 = h_hi[arow0 + kw + 4];
            uint32_t ah3 = h_hi[arow1 + kw + 4];
            uint32_t al0 = h_lo[arow0 + kw];
            uint32_t al1 = h_lo[arow1 + kw];
            uint32_t al2 = h_lo[arow0 + kw + 4];
            uint32_t al3 = h_lo[arow1 + kw + 4];
            #pragma unroll
            for (int j = 0; j < 2; j++) {
                int nr = (nbase + j * 8 + r) * ROWW + kw;
                uint32_t bh0 = u_hi[nr], bh1 = u_hi[nr + 4];
                uint32_t bl0 = u_lo[nr], bl1 = u_lo[nr + 4];
                mma_bf16(c[j], ah0, ah1, ah2, ah3, bh0, bh1);
                mma_bf16(c[j], ah0, ah1, ah2, ah3, bl0, bl1);
                mma_bf16(c[j], al0, al1, al2, al3, bh0, bh1);
            }
        }

        #pragma unroll
        for (int j = 0; j < 2; j++) {
            float* p = part + kseg * (32 * 68) + (mbase + r) * 68 + nbase + j * 8 + 2 * tq;
            *(float2*)p            = make_float2(c[j][0], c[j][1]);
            *(float2*)(p + 8 * 68) = make_float2(c[j][2], c[j][3]);
        }
        __syncthreads();                    // joint: both K-half partials ready

        {
            float4 p0 = *(const float4*)&part[pr * 68 + pj * 4];
            float4 p1 = *(const float4*)&part[32 * 68 + pr * 68 + pj * 4];
            float gi = p0.x + p1.x + xw4.x;
            float gf = p0.y + p1.y + xw4.y;
            float gc = p0.z + p1.z + xw4.z;
            float go = p0.w + p1.w + xw4.w;
            float it_ = 1.f / (1.f + __expf(-gi));
            float ft  = 1.f / (1.f + __expf(-gf));
            float ch  = tanhf(gc);
            float ot  = 1.f / (1.f + __expf(-go));
            float cn  = mr * (ft * cr + it_ * ch);
            cr = cn;
            float hn = ot * tanhf(cn);
            out[(size_t)t * BH + pidx] = hn;
            size_t nb = (size_t)((t + 1) & 1) * (BB * HH);
            __nv_bfloat16 hb = __float2bfloat16(hn);
            g_hBhi[nb + pidx] = hb;
            g_hBlo[nb + pidx] = __float2bfloat16(hn - __bfloat162float(hb));
        }

        __syncthreads();                    // all h(t+1) writes done block-wide
        if (tid == 0) {
            asm volatile("red.release.gpu.global.add.u32 [%0], %1;"
                         :: "l"(ctr_mine), "r"(1u) : "memory");
        }
    }

    g_c[pidx] = cr;
}

// copy h_T (== outputs[S-1]) and c_T into the output tail
__global__ void finalize(float* __restrict__ out)
{
    int i = blockIdx.x * blockDim.x + threadIdx.x;
    if (i < BH) {
        out[(size_t)SS * BH + i]      = out[(size_t)(SS - 1) * BH + i];
        out[(size_t)SS * BH + BH + i] = g_c[i];
    }
}

// ---------------------------------------------------------------------------
extern "C" void kernel_launch(void* const* d_in, const int* in_sizes, int n_in,
                              void* d_out, int out_size)
{
    const float* x     = (const float*)d_in[0];
    const float* h0    = (const float*)d_in[1];
    const float* c0    = (const float*)d_in[2];
    const float* alpha = (const float*)d_in[3];
    const float* beta  = (const float*)d_in[4];
    const float* theta = (const float*)d_in[5];
    const float* tspan = (const float*)d_in[6];
    const float* A     = (const float*)d_in[7];
    const float* Bm    = (const float*)d_in[8];
    const float* C     = (const float*)d_in[9];
    const float* Wi = (const float*)d_in[10];
    const float* Ui = (const float*)d_in[11];
    const float* bi = (const float*)d_in[12];
    const float* Wf = (const float*)d_in[13];
    const float* Uf = (const float*)d_in[14];
    const float* bf = (const float*)d_in[15];
    const float* Wc = (const float*)d_in[16];
    const float* Uc = (const float*)d_in[17];
    const float* bc = (const float*)d_in[18];
    const float* Wo = (const float*)d_in[19];
    const float* Uo = (const float*)d_in[20];
    const float* bo = (const float*)d_in[21];
    float* out = (float*)d_out;

    const int SMEM  = (2 * 64 * ROWW + 2 * 32 * ROWW + 2 * 32 * 68) * 4;  // 217088 B
    const int XSMEM = 2 * STGW * 4;                                        // 147456 B
    cudaFuncSetAttribute(lstm_persist, cudaFuncAttributeMaxDynamicSharedMemorySize, SMEM);
    cudaFuncSetAttribute(xw_mma, cudaFuncAttributeMaxDynamicSharedMemorySize, XSMEM);

    prep_U<<<dim3(16, 16, 4), dim3(32, 8)>>>(Ui, Uf, Uc, Uo);
    prep_W<<<dim3(16, 8, 4), dim3(32, 8)>>>(Wi, Wf, Wc, Wo);
    prep_state<<<(BB * HH + 255) / 256, 256>>>(h0, bi, bf, bc, bo);
    mdhp_kernel<<<BB, 512>>>(alpha, beta, theta, tspan, A, Bm, C);
    xsplit<<<(SS * BB * DD / 4) / 256, 256>>>(x);
    xw_mma<<<dim3(GG / 128, (SS * BB) / 128), 256, XSMEM>>>();
    lstm_persist<<<dim3(32, 4), 512, SMEM>>>(c0, out);
    finalize<<<(BH + 255) / 256, 256>>>(out);
}

// round 17
// speedup vs baseline: 1.2864x; 1.0026x over previous
#include <cuda_runtime.h>
#include <cuda_bf16.h>
#include <math.h>
#include <stdint.h>

// Problem dimensions (fixed by the dataset)
#define SS 512   // timesteps
#define BB 128   // batch
#define DD 256   // input dim
#define HH 512   // hidden
#define GG 2048  // 4*H (gate-interleaved: col n = j*4 + gate)
#define BH (BB*HH)

// Device scratch (no runtime allocation allowed)
__device__ float g_bias[GG];                 // interleaved bias [2048]
__device__ __nv_bfloat16 g_UThi[GG*HH];      // U'^T hi  [2048 n][512 k] bf16
__device__ __nv_bfloat16 g_UTlo[GG*HH];      // U'^T lo
__device__ __nv_bfloat16 g_WThi[GG*DD];      // W'^T hi  [2048 n][256 k] bf16
__device__ __nv_bfloat16 g_WTlo[GG*DD];      // W'^T lo
__device__ __nv_bfloat16 g_xhi[(size_t)SS*BB*DD];  // x hi  [65536 m][256 k] bf16
__device__ __nv_bfloat16 g_xlo[(size_t)SS*BB*DD];  // x lo
__device__ __nv_bfloat16 g_hBhi[2*BB*HH];    // double-buffered h hi [2][128 b][512 k]
__device__ __nv_bfloat16 g_hBlo[2*BB*HH];    // double-buffered h lo
__device__ float g_mdhp[BH];                 // tanh(alpha@A - (beta*ts)@B + theta@C)
__device__ float g_c[BH];                    // final cell state (for finalize)
__device__ float g_xw[(size_t)SS*BB*GG];     // precomputed x@W' + b  (512 MB)
__device__ unsigned g_ctr8[8];               // per-(rowgroup, K-half) barrier counters

// ---------------------------------------------------------------------------
// helpers
// ---------------------------------------------------------------------------
__device__ __forceinline__ void mma_bf16(float* c, uint32_t a0, uint32_t a1,
                                         uint32_t a2, uint32_t a3,
                                         uint32_t b0, uint32_t b1) {
    asm volatile("mma.sync.aligned.m16n8k16.row.col.f32.bf16.bf16.f32 "
        "{%0,%1,%2,%3}, {%4,%5,%6,%7}, {%8,%9}, {%0,%1,%2,%3};"
        : "+f"(c[0]), "+f"(c[1]), "+f"(c[2]), "+f"(c[3])
        : "r"(a0), "r"(a1), "r"(a2), "r"(a3), "r"(b0), "r"(b1));
}
__device__ __forceinline__ void ldsm_x4(uint32_t* r, uint32_t addr) {
    asm volatile("ldmatrix.sync.aligned.m8n8.x4.shared.b16 {%0,%1,%2,%3}, [%4];"
        : "=r"(r[0]), "=r"(r[1]), "=r"(r[2]), "=r"(r[3]) : "r"(addr));
}
__device__ __forceinline__ void ldsm_x2(uint32_t& r0, uint32_t& r1, uint32_t addr) {
    asm volatile("ldmatrix.sync.aligned.m8n8.x2.shared.b16 {%0,%1}, [%2];"
        : "=r"(r0), "=r"(r1) : "r"(addr));
}
__device__ __forceinline__ uint32_t smem_cast(const void* p) {
    return (uint32_t)__cvta_generic_to_shared(p);
}
__device__ __forceinline__ void cp16(uint32_t saddr, const void* g) {
    asm volatile("cp.async.ca.shared.global [%0], [%1], 16;" :: "r"(saddr), "l"(g));
}
__device__ __forceinline__ void cp16cg(uint32_t saddr, const void* g) {
    asm volatile("cp.async.cg.shared.global [%0], [%1], 16;" :: "r"(saddr), "l"(g));
}
#define CP_COMMIT() asm volatile("cp.async.commit_group;" ::: "memory")
#define CP_WAIT(n)  asm volatile("cp.async.wait_group %0;" :: "n"(n) : "memory")
#define BAR_SYNC(id, cnt) asm volatile("bar.sync %0, %1;" :: "r"(id), "r"(cnt) : "memory")

// ---------------------------------------------------------------------------
// prep_U: tile-transpose U_g[512 k][512 j] -> g_UT{hi,lo}[n=4j+g][k], coalesced.
// grid (16 jt, 16 kt, 4 g), block (32, 8)
// ---------------------------------------------------------------------------
__global__ void prep_U(const float* __restrict__ Ui, const float* __restrict__ Uf,
                       const float* __restrict__ Uc, const float* __restrict__ Uo)
{
    __shared__ float tile[32][33];
    const int g = blockIdx.z;
    const float* U = (g == 0) ? Ui : (g == 1) ? Uf : (g == 2) ? Uc : Uo;
    const int j0 = blockIdx.x * 32, k0 = blockIdx.y * 32;
    const int tx = threadIdx.x, ty = threadIdx.y;
    #pragma unroll
    for (int q = 0; q < 4; q++) {
        int kk = ty + q * 8;
        tile[kk][tx] = U[(size_t)(k0 + kk) * HH + j0 + tx];
    }
    __syncthreads();
    #pragma unroll
    for (int q = 0; q < 4; q++) {
        int jj = ty + q * 8;
        float u = tile[tx][jj];                 // = U[k0+tx][j0+jj]
        __nv_bfloat16 hi = __float2bfloat16(u);
        size_t o = (size_t)(4 * (j0 + jj) + g) * HH + k0 + tx;
        g_UThi[o] = hi;
        g_UTlo[o] = __float2bfloat16(u - __bfloat162float(hi));
    }
}

// prep_W: same for W_g[256 k][512 j] -> g_WT{hi,lo}[n][k]. grid (16 jt, 8 kt, 4 g)
__global__ void prep_W(const float* __restrict__ Wi, const float* __restrict__ Wf,
                       const float* __restrict__ Wc, const float* __restrict__ Wo)
{
    __shared__ float tile[32][33];
    const int g = blockIdx.z;
    const float* W = (g == 0) ? Wi : (g == 1) ? Wf : (g == 2) ? Wc : Wo;
    const int j0 = blockIdx.x * 32, k0 = blockIdx.y * 32;
    const int tx = threadIdx.x, ty = threadIdx.y;
    #pragma unroll
    for (int q = 0; q < 4; q++) {
        int kk = ty + q * 8;
        tile[kk][tx] = W[(size_t)(k0 + kk) * HH + j0 + tx];
    }
    __syncthreads();
    #pragma unroll
    for (int q = 0; q < 4; q++) {
        int jj = ty + q * 8;
        float w = tile[tx][jj];
        __nv_bfloat16 hi = __float2bfloat16(w);
        size_t o = (size_t)(4 * (j0 + jj) + g) * DD + k0 + tx;
        g_WThi[o] = hi;
        g_WTlo[o] = __float2bfloat16(w - __bfloat162float(hi));
    }
}

// split x into bf16 hi/lo (16.7M elements, 4 per thread)
__global__ void xsplit(const float* __restrict__ x)
{
    size_t i = (size_t)blockIdx.x * blockDim.x + threadIdx.x;   // float4 index
    float4 v = *((const float4*)x + i);
    __nv_bfloat16 h0 = __float2bfloat16(v.x);
    __nv_bfloat16 h1 = __float2bfloat16(v.y);
    __nv_bfloat16 h2 = __float2bfloat16(v.z);
    __nv_bfloat16 h3 = __float2bfloat16(v.w);
    __nv_bfloat16 l0 = __float2bfloat16(v.x - __bfloat162float(h0));
    __nv_bfloat16 l1 = __float2bfloat16(v.y - __bfloat162float(h1));
    __nv_bfloat16 l2 = __float2bfloat16(v.z - __bfloat162float(h2));
    __nv_bfloat16 l3 = __float2bfloat16(v.w - __bfloat162float(h3));
    ushort4 ph = make_ushort4(__bfloat16_as_ushort(h0), __bfloat16_as_ushort(h1),
                              __bfloat16_as_ushort(h2), __bfloat16_as_ushort(h3));
    ushort4 pl = make_ushort4(__bfloat16_as_ushort(l0), __bfloat16_as_ushort(l1),
                              __bfloat16_as_ushort(l2), __bfloat16_as_ushort(l3));
    *((ushort4*)g_xhi + i) = ph;
    *((ushort4*)g_xlo + i) = pl;
}

// ---------------------------------------------------------------------------
// mdhp = tanh(alpha @ A - (beta*tspan) @ B + theta @ C)   [B,H]
// ---------------------------------------------------------------------------
__global__ void mdhp_kernel(const float* __restrict__ alpha, const float* __restrict__ beta,
                            const float* __restrict__ theta, const float* __restrict__ tspan,
                            const float* __restrict__ A, const float* __restrict__ Bm,
                            const float* __restrict__ C)
{
    int b = blockIdx.x;
    int j = threadIdx.x;   // 0..511
    __shared__ float sa[256], sb[256], st[16];
    float ts = tspan[b];
    if (j < 256) {
        sa[j] = alpha[b * 256 + j];
        sb[j] = beta[b * 256 + j] * ts;
    }
    if (j < 16) st[j] = theta[b * 16 + j];
    __syncthreads();
    float acc = 0.f;
    #pragma unroll 8
    for (int k = 0; k < 256; k++)
        acc += sa[k] * A[k * 512 + j] - sb[k] * Bm[k * 512 + j];
    #pragma unroll
    for (int k = 0; k < 16; k++)
        acc += st[k] * C[k * 512 + j];
    g_mdhp[b * 512 + j] = tanhf(acc);
}

// zero barrier counters + bf16-split h0 + interleaved bias
__global__ void prep_state(const float* __restrict__ h0,
                           const float* __restrict__ bi, const float* __restrict__ bf,
                           const float* __restrict__ bc, const float* __restrict__ bo)
{
    int i = blockIdx.x * blockDim.x + threadIdx.x;
    if (i < 8) g_ctr8[i] = 0u;
    if (i < GG) {
        int j = i >> 2, g = i & 3;
        const float* bptr = (g == 0) ? bi : (g == 1) ? bf : (g == 2) ? bc : bo;
        g_bias[i] = bptr[j];
    }
    if (i < BB * HH) {
        float v = h0[i];                       // i = b*512 + k
        __nv_bfloat16 hi = __float2bfloat16(v);
        g_hBhi[i] = hi;
        g_hBlo[i] = __float2bfloat16(v - __bfloat162float(hi));
    }
}

// ---------------------------------------------------------------------------
// xW GEMM on mma.sync bf16 (2-way split, 3-term product), ldmatrix loads,
// cp.async double-buffered stages.
//   g_xw[65536, 2048] = x[65536, 256] @ W'[256, 2048] + bias
// NEW: 512 threads = 16 warps (4 M x 4 N), warp tile 32x32 — 4 warps/SMSP to
// cover ldsm latency and lift tensor-pipe utilization.
// ---------------------------------------------------------------------------
#define ROWX 36                 // uint32 words per padded row (32 data words)
#define STGW (4 * 128 * ROWX)   // words per stage (a_hi,a_lo,b_hi,b_lo)
__global__ __launch_bounds__(512, 1) void xw_mma()
{
    extern __shared__ __align__(16) uint32_t xs[];

    const int tid  = threadIdx.x;
    const int lane = tid & 31;
    const int wid  = tid >> 5;              // 0..15
    const int mbase = (wid & 3) * 32;       // 0,32,64,96
    const int nbase = (wid >> 2) * 32;      // 0,32,64,96
    const int r  = lane >> 2;               // 0..7
    const int tq = lane & 3;                // 0..3
    const int n0 = blockIdx.x * 128;
    const int m0 = blockIdx.y * 128;

    const uint32_t smBase = smem_cast(xs);
    const uint32_t STGB = STGW * 4;                 // stage bytes
    const uint32_t ARRB = 128 * ROWX * 4;           // array bytes

    const uint32_t aRowOff = ((mbase + (lane & 15)) * ROWX + (lane >> 4) * 4) << 2;
    const uint32_t aHiB = smBase + aRowOff;
    const uint32_t aLoB = smBase + ARRB + aRowOff;
    const uint32_t bRowOff = ((nbase + (lane & 7)) * ROWX + ((lane >> 3) & 1) * 4) << 2;
    const uint32_t bHiB = smBase + 2 * ARRB + bRowOff;
    const uint32_t bLoB = smBase + 3 * ARRB + bRowOff;
    const uint32_t FSTRIDE = (16 * ROWX) << 2;   // f: +16 rows
    const uint32_t JSTRIDE = (8 * ROWX) << 2;    // j: +8 rows

    float c[2][4][4];
    #pragma unroll
    for (int f = 0; f < 2; f++)
        #pragma unroll
        for (int j = 0; j < 4; j++)
            #pragma unroll
            for (int q = 0; q < 4; q++) c[f][j][q] = 0.f;

    auto load_stage = [&](int s, int kc) {
        const int k0 = kc * 64;
        const uint32_t sb = smBase + s * STGB;
        #pragma unroll
        for (int q = 0; q < 2; q++) {
            int u = tid + q * 512;          // 0..1023
            int row = u >> 3;               // 0..127
            int c4  = u & 7;
            uint32_t so = (row * ROWX + c4 * 4) << 2;
            cp16(sb + so,            (const void*)((const uint4*)(g_xhi  + (size_t)(m0 + row) * DD + k0) + c4));
            cp16(sb + ARRB + so,     (const void*)((const uint4*)(g_xlo  + (size_t)(m0 + row) * DD + k0) + c4));
            cp16(sb + 2 * ARRB + so, (const void*)((const uint4*)(g_WThi + (size_t)(n0 + row) * DD + k0) + c4));
            cp16(sb + 3 * ARRB + so, (const void*)((const uint4*)(g_WTlo + (size_t)(n0 + row) * DD + k0) + c4));
        }
    };

    load_stage(0, 0);
    CP_COMMIT();

    for (int kc = 0; kc < 4; kc++) {
        if (kc < 3) {
            load_stage((kc + 1) & 1, kc + 1);
            CP_COMMIT();
            CP_WAIT(1);
        } else {
            CP_WAIT(0);
        }
        __syncthreads();

        const uint32_t so = (kc & 1) * STGB;
        #pragma unroll
        for (int ks = 0; ks < 4; ks++) {
            const uint32_t ksOff = so + ks * 32;
            uint32_t ah[2][4], al[2][4];
            ldsm_x4(ah[0], aHiB + ksOff);
            ldsm_x4(ah[1], aHiB + FSTRIDE + ksOff);
            ldsm_x4(al[0], aLoB + ksOff);
            ldsm_x4(al[1], aLoB + FSTRIDE + ksOff);
            #pragma unroll
            for (int j = 0; j < 4; j++) {
                uint32_t bh0, bh1, bl0, bl1;
                ldsm_x2(bh0, bh1, bHiB + j * JSTRIDE + ksOff);
                ldsm_x2(bl0, bl1, bLoB + j * JSTRIDE + ksOff);
                #pragma unroll
                for (int f = 0; f < 2; f++) {
                    mma_bf16(c[f][j], ah[f][0], ah[f][1], ah[f][2], ah[f][3], bh0, bh1);
                    mma_bf16(c[f][j], ah[f][0], ah[f][1], ah[f][2], ah[f][3], bl0, bl1);
                    mma_bf16(c[f][j], al[f][0], al[f][1], al[f][2], al[f][3], bh0, bh1);
                }
            }
        }
        __syncthreads();
    }

    #pragma unroll
    for (int f = 0; f < 2; f++) {
        int row0 = m0 + mbase + f * 16 + r;
        #pragma unroll
        for (int j = 0; j < 4; j++) {
            int col = n0 + nbase + j * 8 + 2 * tq;
            float2 bb = *(const float2*)&g_bias[col];
            float2 o0 = make_float2(c[f][j][0] + bb.x, c[f][j][1] + bb.y);
            float2 o1 = make_float2(c[f][j][2] + bb.x, c[f][j][3] + bb.y);
            __stcs((float2*)&g_xw[(size_t)row0 * GG + col], o0);
            __stcs((float2*)&g_xw[(size_t)(row0 + 8) * GG + col], o1);
        }
    }
}

// ---------------------------------------------------------------------------
// Persistent LSTM recurrence on mma.sync bf16 — unchanged from round 16
// (split half-barriers, cp.async.cg staging, proven).
// ---------------------------------------------------------------------------
#define ROWW 260   // uint32 words per padded bf16 row (520 bf16; 256 data words)
__global__ __launch_bounds__(512) void lstm_persist(const float* __restrict__ c0,
                                                    float* __restrict__ out)
{
    extern __shared__ __align__(16) uint32_t smw[];
    uint32_t* u_hi = smw;                               // [64][260]
    uint32_t* u_lo = smw + 64 * ROWW;                   // [64][260]
    uint32_t* h_hi = smw + 2 * 64 * ROWW;               // [32][260]
    uint32_t* h_lo = smw + 2 * 64 * ROWW + 32 * ROWW;   // [32][260]
    float*    part = (float*)(smw + 2 * 64 * ROWW + 2 * 32 * ROWW); // [2][32][68]

    const int tid = threadIdx.x;
    const int bx  = blockIdx.x;            // 0..31 col block
    const int rg  = blockIdx.y;            // 0..3  row group
    const int n0  = bx * 64;               // interleaved gate-col base
    const int b0  = rg * 32;               // batch row base

    const int lane = tid & 31;
    const int wid  = tid >> 5;             // 0..15
    const int kseg  = wid >> 3;            // 0..1  K half (also staging group)
    const int ow    = wid & 7;             // 0..7  output warp
    const int mbase = (ow >> 2) * 16;      // 0 or 16
    const int nbase = (ow & 3) * 16;       // 0,16,32,48
    const int r  = lane >> 2;              // 0..7
    const int tq = lane & 3;               // 0..3

    const int pr = tid >> 4;               // 0..31
    const int pj = tid & 15;               // 0..15
    const int jglob = bx * 16 + pj;
    const int pidx = (b0 + pr) * HH + jglob;

    const int gt = tid & 255;              // thread id within kseg group
    unsigned* ctr_mine = &g_ctr8[rg * 2 + (bx >> 4)];   // this block arrives here
    unsigned* ctr_need = &g_ctr8[rg * 2 + kseg];        // this group waits here

    // ---- load persistent U'^T slice (bf16 hi/lo) ----
    #pragma unroll
    for (int q = 0; q < 8; q++) {
        int u = tid + q * 512;              // 0..4095
        int row = u >> 6;                   // 0..63
        int c4  = u & 63;
        uint4 vh = *((const uint4*)(g_UThi + (size_t)(n0 + row) * HH) + c4);
        uint4 vl = *((const uint4*)(g_UTlo + (size_t)(n0 + row) * HH) + c4);
        *(uint4*)(u_hi + row * ROWW + c4 * 4) = vh;
        *(uint4*)(u_lo + row * ROWW + c4 * 4) = vl;
    }

    float cr = c0[pidx];
    float mr = g_mdhp[pidx];
    __syncthreads();

    for (int t = 0; t < SS; t++) {
        // prefetch xw quad (DRAM latency overlaps the wait below)
        float4 xw4 = *(const float4*)&g_xw[((size_t)t * BB + b0 + pr) * GG + n0 + pj * 4];

        // ---- group-level wait: producers of our K-half finished step t-1 ----
        if (gt == 0) {
            unsigned target = (unsigned)t * 16u;
            unsigned cur;
            do {
                asm volatile("ld.acquire.gpu.global.u32 %0, [%1];"
                             : "=r"(cur) : "l"(ctr_need) : "memory");
            } while (cur < target);
        }
        BAR_SYNC(1 + kseg, 256);

        // ---- stage own K-half of h via cp.async.cg (L2-coherent) ----
        const __nv_bfloat16* hbh = g_hBhi + (size_t)(t & 1) * (BB * HH);
        const __nv_bfloat16* hbl = g_hBlo + (size_t)(t & 1) * (BB * HH);
        #pragma unroll
        for (int q = 0; q < 4; q++) {
            int u = gt + q * 256;           // 0..1023
            int row = u >> 5;               // 0..31
            int c4  = kseg * 32 + (u & 31); // this group's K-half
            uint32_t so = (row * ROWW + c4 * 4) << 2;
            cp16cg(smem_cast(h_hi) + so, (const void*)((const uint4*)(hbh + (size_t)(b0 + row) * HH) + c4));
            cp16cg(smem_cast(h_lo) + so, (const void*)((const uint4*)(hbl + (size_t)(b0 + row) * HH) + c4));
        }
        CP_COMMIT();
        CP_WAIT(0);
        BAR_SYNC(1 + kseg, 256);            // group-local: own K-half staged

        // ---- GEMM: warp tile m16 x n16, this group's K half ----
        float c[2][4] = {};
        const int arow0 = (mbase + r) * ROWW;
        const int arow1 = (mbase + r + 8) * ROWW;
        #pragma unroll 4
        for (int ks = 0; ks < 16; ks++) {
            int kw = kseg * 128 + ks * 8 + tq;
            uint32_t ah0 = h_hi[arow0 + kw];
            uint32_t ah1 = h_hi[arow1 + kw];
            uint32_t ah2 = h_hi[arow0 + kw + 4];
            uint32_t ah3 = h_hi[arow1 + kw + 4];
            uint32_t al0 = h_lo[arow0 + kw];
            uint32_t al1 = h_lo[arow1 + kw];
            uint32_t al2 = h_lo[arow0 + kw + 4];
            uint32_t al3 = h_lo[arow1 + kw + 4];
            #pragma unroll
            for (int j = 0; j < 2; j++) {
                int nr = (nbase + j * 8 + r) * ROWW + kw;
                uint32_t bh0 = u_hi[nr], bh1 = u_hi[nr + 4];
                uint32_t bl0 = u_lo[nr], bl1 = u_lo[nr + 4];
                mma_bf16(c[j], ah0, ah1, ah2, ah3, bh0, bh1);
                mma_bf16(c[j], ah0, ah1, ah2, ah3, bl0, bl1);
                mma_bf16(c[j], al0, al1, al2, al3, bh0, bh1);
            }
        }

        #pragma unroll
        for (int j = 0; j < 2; j++) {
            float* p = part + kseg * (32 * 68) + (mbase + r) * 68 + nbase + j * 8 + 2 * tq;
            *(float2*)p            = make_float2(c[j][0], c[j][1]);
            *(float2*)(p + 8 * 68) = make_float2(c[j][2], c[j][3]);
        }
        __syncthreads();                    // joint: both K-half partials ready

        {
            float4 p0 = *(const float4*)&part[pr * 68 + pj * 4];
            float4 p1 = *(const float4*)&part[32 * 68 + pr * 68 + pj * 4];
            float gi = p0.x + p1.x + xw4.x;
            float gf = p0.y + p1.y + xw4.y;
            float gc = p0.z + p1.z + xw4.z;
            float go = p0.w + p1.w + xw4.w;
            float it_ = 1.f / (1.f + __expf(-gi));
            float ft  = 1.f / (1.f + __expf(-gf));
            float ch  = tanhf(gc);
            float ot  = 1.f / (1.f + __expf(-go));
            float cn  = mr * (ft * cr + it_ * ch);
            cr = cn;
            float hn = ot * tanhf(cn);
            out[(size_t)t * BH + pidx] = hn;
            size_t nb = (size_t)((t + 1) & 1) * (BB * HH);
            __nv_bfloat16 hb = __float2bfloat16(hn);
            g_hBhi[nb + pidx] = hb;
            g_hBlo[nb + pidx] = __float2bfloat16(hn - __bfloat162float(hb));
        }

        __syncthreads();                    // all h(t+1) writes done block-wide
        if (tid == 0) {
            asm volatile("red.release.gpu.global.add.u32 [%0], %1;"
                         :: "l"(ctr_mine), "r"(1u) : "memory");
        }
    }

    g_c[pidx] = cr;
}

// copy h_T (== outputs[S-1]) and c_T into the output tail
__global__ void finalize(float* __restrict__ out)
{
    int i = blockIdx.x * blockDim.x + threadIdx.x;
    if (i < BH) {
        out[(size_t)SS * BH + i]      = out[(size_t)(SS - 1) * BH + i];
        out[(size_t)SS * BH + BH + i] = g_c[i];
    }
}

// ---------------------------------------------------------------------------
extern "C" void kernel_launch(void* const* d_in, const int* in_sizes, int n_in,
                              void* d_out, int out_size)
{
    const float* x     = (const float*)d_in[0];
    const float* h0    = (const float*)d_in[1];
    const float* c0    = (const float*)d_in[2];
    const float* alpha = (const float*)d_in[3];
    const float* beta  = (const float*)d_in[4];
    const float* theta = (const float*)d_in[5];
    const float* tspan = (const float*)d_in[6];
    const float* A     = (const float*)d_in[7];
    const float* Bm    = (const float*)d_in[8];
    const float* C     = (const float*)d_in[9];
    const float* Wi = (const float*)d_in[10];
    const float* Ui = (const float*)d_in[11];
    const float* bi = (const float*)d_in[12];
    const float* Wf = (const float*)d_in[13];
    const float* Uf = (const float*)d_in[14];
    const float* bf = (const float*)d_in[15];
    const float* Wc = (const float*)d_in[16];
    const float* Uc = (const float*)d_in[17];
    const float* bc = (const float*)d_in[18];
    const float* Wo = (const float*)d_in[19];
    const float* Uo = (const float*)d_in[20];
    const float* bo = (const float*)d_in[21];
    float* out = (float*)d_out;

    const int SMEM  = (2 * 64 * ROWW + 2 * 32 * ROWW + 2 * 32 * 68) * 4;  // 217088 B
    const int XSMEM = 2 * STGW * 4;                                        // 147456 B
    cudaFuncSetAttribute(lstm_persist, cudaFuncAttributeMaxDynamicSharedMemorySize, SMEM);
    cudaFuncSetAttribute(xw_mma, cudaFuncAttributeMaxDynamicSharedMemorySize, XSMEM);

    prep_U<<<dim3(16, 16, 4), dim3(32, 8)>>>(Ui, Uf, Uc, Uo);
    prep_W<<<dim3(16, 8, 4), dim3(32, 8)>>>(Wi, Wf, Wc, Wo);
    prep_state<<<(BB * HH + 255) / 256, 256>>>(h0, bi, bf, bc, bo);
    mdhp_kernel<<<BB, 512>>>(alpha, beta, theta, tspan, A, Bm, C);
    xsplit<<<(SS * BB * DD / 4) / 256, 256>>>(x);
    xw_mma<<<dim3(GG / 128, (SS * BB) / 128), 512, XSMEM>>>();
    lstm_persist<<<dim3(32, 4), 512, SMEM>>>(c0, out);
    finalize<<<(BH + 255) / 256, 256>>>(out);
}